// round 3
// baseline (speedup 1.0000x reference)
#include <cuda_runtime.h>
#include <cuda_bf16.h>
#include <mma.h>
using namespace nvcuda;

#define BB 8
#define SS 4096
#define DD 1024
#define MM 32
#define KA 3
#define RR 64
#define NROWS (BB*SS)

// ---------------- scratch (device globals; no allocations allowed) ----------------
__device__ float g_scores[NROWS];
__device__ int   g_aidx[BB*KA];
__device__ float g_apos[BB*KA];
__device__ float g_logits[BB*KA*MM];
__device__ float g_ua[BB*KA*MM*RR];
__device__ float g_w[BB*KA*MM];
__device__ float g_low[BB*KA*RR];
__device__ float g_Z[BB*KA];
__device__ float g_transp[BB*KA*MM*DD];
__device__ float g_trans[BB*KA*DD];
__device__ float g_tsaug[(size_t)NROWS*DD];
__device__ float g_tsn[(size_t)NROWS*DD];
__device__ float g_ptn[(size_t)NROWS*DD];
__device__ float g_gate[NROWS];
__device__ float g_shared[(size_t)NROWS*DD];
__device__ __nv_bfloat16 g_a2[(size_t)NROWS*DD];
__device__ __nv_bfloat16 g_a3[(size_t)NROWS*DD];

// ---------------- K0: anchor scores ----------------
__global__ void __launch_bounds__(256) k_scores(const float* __restrict__ pt,
                                                const float* __restrict__ aw,
                                                const float* __restrict__ ab) {
    int gw = (blockIdx.x * blockDim.x + threadIdx.x) >> 5;
    int lane = threadIdx.x & 31;
    if (gw >= NROWS) return;
    const float4* p = (const float4*)(pt + (size_t)gw * DD);
    const float4* w = (const float4*)aw;
    float s = 0.f;
#pragma unroll
    for (int i = 0; i < 8; i++) {
        float4 a = p[lane + 32 * i];
        float4 b = w[lane + 32 * i];
        s += a.x * b.x + a.y * b.y + a.z * b.z + a.w * b.w;
    }
#pragma unroll
    for (int o = 16; o; o >>= 1) s += __shfl_down_sync(0xffffffffu, s, o);
    if (!lane) g_scores[gw] = s + ab[0];
}

// ---------------- K1: top-3 per batch (jax top_k tie-break: lower index wins) ----------------
__global__ void k_top3(const float* __restrict__ pos) {
    __shared__ float sv[256];
    __shared__ int   si[256];
    __shared__ int   chosen[KA];
    int b = blockIdx.x, tid = threadIdx.x;
    const float* sc = g_scores + b * SS;
    for (int k = 0; k < KA; k++) {
        float bv = -3.4e38f; int bi = SS;
        for (int s = tid; s < SS; s += 256) {
            bool used = false;
            for (int j = 0; j < k; j++) used |= (chosen[j] == s);
            if (used) continue;
            float v = sc[s];
            if (v > bv || (v == bv && s < bi)) { bv = v; bi = s; }
        }
        sv[tid] = bv; si[tid] = bi;
        __syncthreads();
        for (int o = 128; o; o >>= 1) {
            if (tid < o) {
                if (sv[tid + o] > sv[tid] || (sv[tid + o] == sv[tid] && si[tid + o] < si[tid])) {
                    sv[tid] = sv[tid + o]; si[tid] = si[tid + o];
                }
            }
            __syncthreads();
        }
        if (tid == 0) {
            chosen[k] = si[0];
            g_aidx[b * KA + k] = si[0];
            g_apos[b * KA + k] = pos[si[0]];
        }
        __syncthreads();
    }
}

// ---------------- K2: per (b,k,m): cosine logit + u_a[r] = sum_d av[d]*trans_a[m,d,r] ----------------
__global__ void __launch_bounds__(128) k_basis(const float* __restrict__ pt,
                                               const float* __restrict__ cent,
                                               const float* __restrict__ ta) {
    __shared__ float av[DD];
    __shared__ float r1[128], r2[128], r3[128];
    int id = blockIdx.x;
    int m = id % MM, bk = id / MM;
    int b = bk / KA;
    int tid = threadIdx.x;
    const float* prow = pt + ((size_t)b * SS + g_aidx[bk]) * DD;
    const float* crow = cent + (size_t)m * DD;
    float pa = 0.f, pc = 0.f, pd = 0.f;
    for (int d = tid; d < DD; d += 128) {
        float a = prow[d], c = crow[d];
        av[d] = a; pa += a * a; pc += c * c; pd += a * c;
    }
    r1[tid] = pa; r2[tid] = pc; r3[tid] = pd;
    __syncthreads();
    for (int o = 64; o; o >>= 1) {
        if (tid < o) { r1[tid] += r1[tid + o]; r2[tid] += r2[tid + o]; r3[tid] += r3[tid + o]; }
        __syncthreads();
    }
    if (tid == 0) {
        float na = sqrtf(r1[0]), nc = sqrtf(r2[0]);
        g_logits[id] = r3[0] / (fmaxf(na, 1e-6f) * fmaxf(nc, 1e-6f));
    }
    __syncthreads();
    int r = tid & 63, h = tid >> 6;
    const float* tap = ta + (size_t)m * DD * RR + r;
    float u = 0.f;
    int d0 = h * 512;
#pragma unroll 8
    for (int d = d0; d < d0 + 512; d++) u += av[d] * tap[(size_t)d * RR];
    r1[tid] = u;
    __syncthreads();
    if (h == 0) g_ua[(size_t)id * RR + r] = r1[r] + r1[r + 64];
}

// ---------------- K3: per (b,k): softmax over modes, low[r], spread normalizer Z ----------------
__global__ void __launch_bounds__(128) k_mix(const float* __restrict__ pos) {
    __shared__ float w[MM];
    __shared__ float red[128];
    int bk = blockIdx.x, tid = threadIdx.x;
    if (tid == 0) {
        float mx = -3.4e38f;
        for (int m = 0; m < MM; m++) mx = fmaxf(mx, g_logits[bk * MM + m]);
        float ssum = 0.f;
        for (int m = 0; m < MM; m++) { float e = expf(g_logits[bk * MM + m] - mx); w[m] = e; ssum += e; }
        float inv = 1.0f / ssum;
        for (int m = 0; m < MM; m++) w[m] *= inv;
    }
    __syncthreads();
    if (tid < MM) g_w[bk * MM + tid] = w[tid];
    if (tid < RR) {
        float lo = 0.f;
        for (int m = 0; m < MM; m++) lo += w[m] * g_ua[(size_t)(bk * MM + m) * RR + tid];
        g_low[bk * RR + tid] = lo;
    }
    float p = g_apos[bk];
    float z = 0.f;
    for (int s = tid; s < SS; s += 128) {
        float d = fabsf(pos[s] - p);
        if (d <= 8.0f) z += expf(-d * 0.125f);
    }
    red[tid] = z;
    __syncthreads();
    for (int o = 64; o; o >>= 1) { if (tid < o) red[tid] += red[tid + o]; __syncthreads(); }
    if (tid == 0) g_Z[bk] = red[0];
}

// ---------------- K4: per (b,k,m): partial translated (deterministic, no atomics) ----------------
__global__ void __launch_bounds__(128) k_translate(const float* __restrict__ tb) {
    __shared__ float low[RR];
    __shared__ float wv;
    int id = blockIdx.x;
    int m = id % MM, bk = id / MM;
    int tid = threadIdx.x;
    if (tid < RR) low[tid] = g_low[bk * RR + tid];
    if (tid == 0) wv = g_w[bk * MM + m];
    __syncthreads();
    float wloc = wv;
    const float4* base = (const float4*)(tb + (size_t)m * DD * RR);
#pragma unroll
    for (int j = 0; j < 8; j++) {
        int d = tid + 128 * j;
        const float4* rp = base + (size_t)d * (RR / 4);
        float acc = 0.f;
#pragma unroll
        for (int i = 0; i < 16; i++) {
            float4 v = rp[i];
            acc += low[4 * i] * v.x + low[4 * i + 1] * v.y + low[4 * i + 2] * v.z + low[4 * i + 3] * v.w;
        }
        g_transp[(size_t)id * DD + d] = wloc * acc;
    }
}

__global__ void __launch_bounds__(256) k_tcombine() {
    int bk = blockIdx.x, tid = threadIdx.x;
    for (int d = tid; d < DD; d += 256) {
        float s = 0.f;
        for (int m = 0; m < MM; m++) s += g_transp[(size_t)(bk * MM + m) * DD + d];
        g_trans[bk * DD + d] = s;
    }
}

// ---------------- block reduce helper ----------------
__device__ __forceinline__ float2 bred2(float2 v, float* red) {
    int tid = threadIdx.x;
#pragma unroll
    for (int o = 16; o; o >>= 1) {
        v.x += __shfl_down_sync(0xffffffffu, v.x, o);
        v.y += __shfl_down_sync(0xffffffffu, v.y, o);
    }
    if ((tid & 31) == 0) { red[tid >> 5] = v.x; red[8 + (tid >> 5)] = v.y; }
    __syncthreads();
    if (tid == 0) {
        float a = 0.f, b = 0.f;
        for (int i = 0; i < 8; i++) { a += red[i]; b += red[8 + i]; }
        red[0] = a; red[8] = b;
    }
    __syncthreads();
    float2 r = make_float2(red[0], red[8]);
    __syncthreads();
    return r;
}

// ---------------- K5: fused row kernel (anchor update + 3 LNs + gate) ----------------
__global__ void __launch_bounds__(256) k_rows(
    const float* __restrict__ ts, const float* __restrict__ pt,
    const float* __restrict__ pos, const float* __restrict__ stab,
    const float* __restrict__ og, const float* __restrict__ ob,
    const float* __restrict__ tg, const float* __restrict__ tb2,
    const float* __restrict__ pg, const float* __restrict__ pb) {
    __shared__ float red[16];
    int row = blockIdx.x;
    int b = row / SS, s = row % SS;
    int tid = threadIdx.x;
    size_t base = (size_t)row * DD;
    float4 tsv = ((const float4*)(ts + base))[tid];
    float4 ptv = ((const float4*)(pt + base))[tid];
    float ps = pos[s];
    float4 upd = make_float4(0.f, 0.f, 0.f, 0.f);
#pragma unroll
    for (int k = 0; k < KA; k++) {
        int bk = b * KA + k;
        float dist = fabsf(ps - g_apos[bk]);
        if (dist <= 8.0f) {
            float c = expf(-dist * 0.125f) / g_Z[bk];
            float4 t = ((const float4*)(g_trans + (size_t)bk * DD))[tid];
            upd.x += c * t.x; upd.y += c * t.y; upd.z += c * t.z; upd.w += c * t.w;
        }
    }
    float4 x = make_float4(tsv.x + upd.x, tsv.y + upd.y, tsv.z + upd.z, tsv.w + upd.w);
    const float invD = 1.0f / DD;
    // LN1 (out_norm)
    float2 s1 = bred2(make_float2(x.x + x.y + x.z + x.w,
                                  x.x * x.x + x.y * x.y + x.z * x.z + x.w * x.w), red);
    float mu = s1.x * invD;
    float var = s1.y * invD - mu * mu;
    float rs = rsqrtf(var + 1e-5f);
    float4 gv = ((const float4*)og)[tid], bv = ((const float4*)ob)[tid];
    float4 aug;
    aug.x = (x.x - mu) * rs * gv.x + bv.x;
    aug.y = (x.y - mu) * rs * gv.y + bv.y;
    aug.z = (x.z - mu) * rs * gv.z + bv.z;
    aug.w = (x.w - mu) * rs * gv.w + bv.w;
    ((float4*)(g_tsaug + base))[tid] = aug;
    // LN2 (ts_norm)
    float2 s2 = bred2(make_float2(aug.x + aug.y + aug.z + aug.w,
                                  aug.x * aug.x + aug.y * aug.y + aug.z * aug.z + aug.w * aug.w), red);
    float mu2 = s2.x * invD;
    float rs2 = rsqrtf(s2.y * invD - mu2 * mu2 + 1e-5f);
    float4 gv2 = ((const float4*)tg)[tid], bv2 = ((const float4*)tb2)[tid];
    float4 tn;
    tn.x = (aug.x - mu2) * rs2 * gv2.x + bv2.x;
    tn.y = (aug.y - mu2) * rs2 * gv2.y + bv2.y;
    tn.z = (aug.z - mu2) * rs2 * gv2.z + bv2.z;
    tn.w = (aug.w - mu2) * rs2 * gv2.w + bv2.w;
    ((float4*)(g_tsn + base))[tid] = tn;
    // pt LN
    float2 s3 = bred2(make_float2(ptv.x + ptv.y + ptv.z + ptv.w,
                                  ptv.x * ptv.x + ptv.y * ptv.y + ptv.z * ptv.z + ptv.w * ptv.w), red);
    float mu3 = s3.x * invD;
    float rs3 = rsqrtf(s3.y * invD - mu3 * mu3 + 1e-5f);
    float4 gv3 = ((const float4*)pg)[tid], bv3 = ((const float4*)pb)[tid];
    float4 pn;
    pn.x = (ptv.x - mu3) * rs3 * gv3.x + bv3.x;
    pn.y = (ptv.y - mu3) * rs3 * gv3.y + bv3.y;
    pn.z = (ptv.z - mu3) * rs3 * gv3.z + bv3.z;
    pn.w = (ptv.w - mu3) * rs3 * gv3.w + bv3.w;
    ((float4*)(g_ptn + base))[tid] = pn;
    // cosine / gate
    float2 s4 = bred2(make_float2(tn.x * pn.x + tn.y * pn.y + tn.z * pn.z + tn.w * pn.w,
                                  tn.x * tn.x + tn.y * tn.y + tn.z * tn.z + tn.w * tn.w), red);
    float2 s5 = bred2(make_float2(pn.x * pn.x + pn.y * pn.y + pn.z * pn.z + pn.w * pn.w, 0.f), red);
    if (tid == 0) {
        float cosv = s4.x / (fmaxf(sqrtf(s4.y), 1e-6f) * fmaxf(sqrtf(s5.x), 1e-6f));
        float ag = 0.5f * (1.0f + cosv);
        float z = (ag - 0.72f) / 0.2f;
        float focus = 0.2f + 0.8f * expf(-0.5f * z * z);
        g_gate[row] = ag * focus * stab[row];
    }
}

// ---------------- K7: causal pool + form bf16 GEMM inputs ----------------
__global__ void __launch_bounds__(256) k_pool() {
    int row = blockIdx.x;
    int b = row / SS, s = row % SS;
    int tid = threadIdx.x;
    size_t base = (size_t)row * DD;
    int s1 = s - 1; if (s1 < 0) s1 = 0;
    int s2 = s - 2; if (s2 < 0) s2 = 0;
    size_t b1 = ((size_t)b * SS + s1) * DD;
    size_t b2 = ((size_t)b * SS + s2) * DD;
    float4 x0 = ((const float4*)(g_shared + base))[tid];
    float4 x1 = ((const float4*)(g_shared + b1))[tid];
    float4 x2 = ((const float4*)(g_shared + b2))[tid];
    float4 pl;
    pl.x = (x0.x + x1.x + x2.x) / 3.0f;
    pl.y = (x0.y + x1.y + x2.y) / 3.0f;
    pl.z = (x0.z + x1.z + x2.z) / 3.0f;
    pl.w = (x0.w + x1.w + x2.w) / 3.0f;
    float4 tn = ((const float4*)(g_tsn + base))[tid];
    float4 pn = ((const float4*)(g_ptn + base))[tid];
    __nv_bfloat162* o2 = (__nv_bfloat162*)(g_a2 + base) + tid * 2;
    o2[0] = __floats2bfloat162_rn(pl.x - tn.x, pl.y - tn.y);
    o2[1] = __floats2bfloat162_rn(pl.z - tn.z, pl.w - tn.w);
    __nv_bfloat162* o3 = (__nv_bfloat162*)(g_a3 + base) + tid * 2;
    o3[0] = __floats2bfloat162_rn(pl.x - pn.x, pl.y - pn.y);
    o3[1] = __floats2bfloat162_rn(pl.z - pn.z, pl.w - pn.w);
}

// ---------------- K6/K8/K9: WMMA bf16 GEMM, 128x128x32 tiles, fused epilogues ----------------
// MODE 1: shared = [tsn|ptn] @ W[0:2048] + bias + gate*W[2048]   (K=2048)
// MODE 2: ts_out = ts_aug + lb * (a2 @ ts_up_W)                   (K=1024)
// MODE 3: pt_out = pt_hidden + lb * (a3 @ pt_up_W)                (K=1024)
template<int MODE>
__global__ void __launch_bounds__(256) k_gemm(const float* __restrict__ W,
                                              const float* __restrict__ bias,
                                              const float* __restrict__ wlast,
                                              const float* __restrict__ basept,
                                              const float* __restrict__ bscale,
                                              float* __restrict__ outp, int Ktot) {
    extern __shared__ char smem_raw[];
    __nv_bfloat16* As = (__nv_bfloat16*)smem_raw;   // [128][40]
    __nv_bfloat16* Bs = As + 128 * 40;              // [32][136]
    float* Cs = (float*)smem_raw;                   // [128][132] epilogue reuse

    const int tid = threadIdx.x;
    const int bn = blockIdx.x;     // 0..7
    const int bm = blockIdx.y;     // 0..255
    const int row0 = bm * 128, col0 = bn * 128;
    const int wid = tid >> 5, wm = wid & 3, wn = wid >> 2;

    wmma::fragment<wmma::accumulator, 16, 16, 16, float> acc[2][4];
#pragma unroll
    for (int i = 0; i < 2; i++)
#pragma unroll
        for (int j = 0; j < 4; j++) wmma::fill_fragment(acc[i][j], 0.0f);

    const int ar = tid >> 3, ac = (tid & 7) * 4;
    const int br = tid >> 5, bc = (tid & 31) * 4;

    for (int kt = 0; kt < Ktot; kt += 32) {
#pragma unroll
        for (int p = 0; p < 4; p++) {
            int rr = ar + 32 * p;
            size_t grow = (size_t)(row0 + rr);
            int gk = kt + ac;
            __nv_bfloat16* dst = As + rr * 40 + ac;
            if (MODE == 1) {
                const float* src = (gk < DD) ? (g_tsn + grow * DD + gk)
                                             : (g_ptn + grow * DD + (gk - DD));
                float4 v = *(const float4*)src;
                *(__nv_bfloat162*)dst       = __floats2bfloat162_rn(v.x, v.y);
                *(__nv_bfloat162*)(dst + 2) = __floats2bfloat162_rn(v.z, v.w);
            } else {
                const __nv_bfloat16* src = (MODE == 2 ? g_a2 : g_a3) + grow * DD + gk;
                *(uint2*)dst = *(const uint2*)src;
            }
        }
#pragma unroll
        for (int p = 0; p < 4; p++) {
            int rr = br + 8 * p;
            int gk = kt + rr;
            float4 v = *(const float4*)(W + (size_t)gk * DD + col0 + bc);
            __nv_bfloat16* dst = Bs + rr * 136 + bc;
            *(__nv_bfloat162*)dst       = __floats2bfloat162_rn(v.x, v.y);
            *(__nv_bfloat162*)(dst + 2) = __floats2bfloat162_rn(v.z, v.w);
        }
        __syncthreads();
#pragma unroll
        for (int kk = 0; kk < 32; kk += 16) {
            wmma::fragment<wmma::matrix_a, 16, 16, 16, __nv_bfloat16, wmma::row_major> af[2];
            wmma::fragment<wmma::matrix_b, 16, 16, 16, __nv_bfloat16, wmma::row_major> bf[4];
#pragma unroll
            for (int i = 0; i < 2; i++) wmma::load_matrix_sync(af[i], As + (wm * 32 + i * 16) * 40 + kk, 40);
#pragma unroll
            for (int j = 0; j < 4; j++) wmma::load_matrix_sync(bf[j], Bs + kk * 136 + wn * 64 + j * 16, 136);
#pragma unroll
            for (int i = 0; i < 2; i++)
#pragma unroll
                for (int j = 0; j < 4; j++) wmma::mma_sync(acc[i][j], af[i], bf[j], acc[i][j]);
        }
        __syncthreads();
    }
#pragma unroll
    for (int i = 0; i < 2; i++)
#pragma unroll
        for (int j = 0; j < 4; j++)
            wmma::store_matrix_sync(Cs + (wm * 32 + i * 16) * 132 + wn * 64 + j * 16,
                                    acc[i][j], 132, wmma::mem_row_major);
    __syncthreads();
    float blend = 0.0f;
    if (MODE != 1) blend = 0.35f / (1.0f + expf(-bscale[0]));
    for (int e = tid; e < 128 * 128; e += 256) {
        int r = e >> 7, c = e & 127;
        size_t grow = (size_t)(row0 + r);
        int gcol = col0 + c;
        float v = Cs[r * 132 + c];
        if (MODE == 1) {
            v += bias[gcol] + g_gate[grow] * wlast[gcol];
            g_shared[grow * DD + gcol] = v;
        } else if (MODE == 2) {
            float lb = blend * g_gate[grow];
            outp[grow * DD + gcol] = g_tsaug[grow * DD + gcol] + lb * v;
        } else {
            float lb = blend * g_gate[grow];
            outp[grow * DD + gcol] = basept[grow * DD + gcol] + lb * v;
        }
    }
}

// ---------------- launch ----------------
extern "C" void kernel_launch(void* const* d_in, const int* in_sizes, int n_in,
                              void* d_out, int out_size) {
    const float* pt   = (const float*)d_in[0];
    const float* ts   = (const float*)d_in[1];
    const float* pos  = (const float*)d_in[2];
    const float* cent = (const float*)d_in[3];
    const float* stab = (const float*)d_in[4];
    const float* aw   = (const float*)d_in[5];
    const float* ab   = (const float*)d_in[6];
    const float* ta   = (const float*)d_in[7];
    const float* tb   = (const float*)d_in[8];
    const float* og   = (const float*)d_in[9];
    const float* ob   = (const float*)d_in[10];
    const float* tg   = (const float*)d_in[11];
    const float* tb2  = (const float*)d_in[12];
    const float* pg   = (const float*)d_in[13];
    const float* pb   = (const float*)d_in[14];
    const float* sW   = (const float*)d_in[15];
    const float* sb   = (const float*)d_in[16];
    const float* tuW  = (const float*)d_in[17];
    const float* puW  = (const float*)d_in[18];
    const float* bs   = (const float*)d_in[19];
    float* out = (float*)d_out;

    const int GEMM_SMEM = 128 * 132 * 4;  // 67584 B
    cudaFuncSetAttribute(k_gemm<1>, cudaFuncAttributeMaxDynamicSharedMemorySize, GEMM_SMEM);
    cudaFuncSetAttribute(k_gemm<2>, cudaFuncAttributeMaxDynamicSharedMemorySize, GEMM_SMEM);
    cudaFuncSetAttribute(k_gemm<3>, cudaFuncAttributeMaxDynamicSharedMemorySize, GEMM_SMEM);

    k_scores<<<NROWS / 8, 256>>>(pt, aw, ab);
    k_top3<<<BB, 256>>>(pos);
    k_basis<<<BB * KA * MM, 128>>>(pt, cent, ta);
    k_mix<<<BB * KA, 128>>>(pos);
    k_translate<<<BB * KA * MM, 128>>>(tb);
    k_tcombine<<<BB * KA, 256>>>();
    k_rows<<<NROWS, 256>>>(ts, pt, pos, stab, og, ob, tg, tb2, pg, pb);

    dim3 gg(8, 256);
    k_gemm<1><<<gg, 256, GEMM_SMEM>>>(sW, sb, sW + (size_t)2048 * DD, nullptr, nullptr, nullptr, 2048);
    k_pool<<<NROWS, 256>>>();
    k_gemm<2><<<gg, 256, GEMM_SMEM>>>(tuW, nullptr, nullptr, nullptr, bs, out, 1024);
    k_gemm<3><<<gg, 256, GEMM_SMEM>>>(puW, nullptr, nullptr, pt, bs, out + (size_t)NROWS * DD, 1024);
}

// round 4
// speedup vs baseline: 1.0009x; 1.0009x over previous
#include <cuda_runtime.h>
#include <cuda_bf16.h>
#include <mma.h>
using namespace nvcuda;

#define BB 8
#define SS 4096
#define DD 1024
#define MM 32
#define KA 3
#define RR 64
#define NROWS (BB*SS)

// ---------------- scratch (device globals; no allocations allowed) ----------------
__device__ float g_scores[NROWS];
__device__ int   g_aidx[BB*KA];
__device__ float g_apos[BB*KA];
__device__ float g_logits[BB*KA*MM];
__device__ float g_ua[BB*KA*MM*RR];
__device__ float g_w[BB*KA*MM];
__device__ float g_low[BB*KA*RR];
__device__ float g_Z[BB*KA];
__device__ float g_transp[BB*KA*MM*DD];
__device__ float g_trans[BB*KA*DD];
__device__ float g_tsaug[(size_t)NROWS*DD];
__device__ float g_tsn[(size_t)NROWS*DD];
__device__ float g_ptn[(size_t)NROWS*DD];
__device__ float g_gate[NROWS];
__device__ float g_shared[(size_t)NROWS*DD];
__device__ __nv_bfloat16 g_a2[(size_t)NROWS*DD];
__device__ __nv_bfloat16 g_a3[(size_t)NROWS*DD];

// ---------------- K0: anchor scores ----------------
__global__ void __launch_bounds__(256) k_scores(const float* __restrict__ pt,
                                                const float* __restrict__ aw,
                                                const float* __restrict__ ab) {
    int gw = (blockIdx.x * blockDim.x + threadIdx.x) >> 5;
    int lane = threadIdx.x & 31;
    if (gw >= NROWS) return;
    const float4* p = (const float4*)(pt + (size_t)gw * DD);
    const float4* w = (const float4*)aw;
    float s = 0.f;
#pragma unroll
    for (int i = 0; i < 8; i++) {
        float4 a = p[lane + 32 * i];
        float4 b = w[lane + 32 * i];
        s += a.x * b.x + a.y * b.y + a.z * b.z + a.w * b.w;
    }
#pragma unroll
    for (int o = 16; o; o >>= 1) s += __shfl_down_sync(0xffffffffu, s, o);
    if (!lane) g_scores[gw] = s + ab[0];
}

// ---------------- K1: top-3 per batch (jax top_k tie-break: lower index wins) ----------------
__global__ void k_top3(const float* __restrict__ pos) {
    __shared__ float sv[256];
    __shared__ int   si[256];
    __shared__ int   chosen[KA];
    int b = blockIdx.x, tid = threadIdx.x;
    const float* sc = g_scores + b * SS;
    for (int k = 0; k < KA; k++) {
        float bv = -3.4e38f; int bi = SS;
        for (int s = tid; s < SS; s += 256) {
            bool used = false;
            for (int j = 0; j < k; j++) used |= (chosen[j] == s);
            if (used) continue;
            float v = sc[s];
            if (v > bv || (v == bv && s < bi)) { bv = v; bi = s; }
        }
        sv[tid] = bv; si[tid] = bi;
        __syncthreads();
        for (int o = 128; o; o >>= 1) {
            if (tid < o) {
                if (sv[tid + o] > sv[tid] || (sv[tid + o] == sv[tid] && si[tid + o] < si[tid])) {
                    sv[tid] = sv[tid + o]; si[tid] = si[tid + o];
                }
            }
            __syncthreads();
        }
        if (tid == 0) {
            chosen[k] = si[0];
            g_aidx[b * KA + k] = si[0];
            g_apos[b * KA + k] = pos[si[0]];
        }
        __syncthreads();
    }
}

// ---------------- K2: per (b,k,m): cosine logit + u_a[r] = sum_d av[d]*trans_a[m,d,r] ----------------
__global__ void __launch_bounds__(128) k_basis(const float* __restrict__ pt,
                                               const float* __restrict__ cent,
                                               const float* __restrict__ ta) {
    __shared__ float av[DD];
    __shared__ float r1[128], r2[128], r3[128];
    int id = blockIdx.x;
    int m = id % MM, bk = id / MM;
    int b = bk / KA;
    int tid = threadIdx.x;
    const float* prow = pt + ((size_t)b * SS + g_aidx[bk]) * DD;
    const float* crow = cent + (size_t)m * DD;
    float pa = 0.f, pc = 0.f, pd = 0.f;
    for (int d = tid; d < DD; d += 128) {
        float a = prow[d], c = crow[d];
        av[d] = a; pa += a * a; pc += c * c; pd += a * c;
    }
    r1[tid] = pa; r2[tid] = pc; r3[tid] = pd;
    __syncthreads();
    for (int o = 64; o; o >>= 1) {
        if (tid < o) { r1[tid] += r1[tid + o]; r2[tid] += r2[tid + o]; r3[tid] += r3[tid + o]; }
        __syncthreads();
    }
    if (tid == 0) {
        float na = sqrtf(r1[0]), nc = sqrtf(r2[0]);
        g_logits[id] = r3[0] / (fmaxf(na, 1e-6f) * fmaxf(nc, 1e-6f));
    }
    __syncthreads();
    int r = tid & 63, h = tid >> 6;
    const float* tap = ta + (size_t)m * DD * RR + r;
    float u = 0.f;
    int d0 = h * 512;
#pragma unroll 8
    for (int d = d0; d < d0 + 512; d++) u += av[d] * tap[(size_t)d * RR];
    r1[tid] = u;
    __syncthreads();
    if (h == 0) g_ua[(size_t)id * RR + r] = r1[r] + r1[r + 64];
}

// ---------------- K3: per (b,k): softmax over modes, low[r], spread normalizer Z ----------------
__global__ void __launch_bounds__(128) k_mix(const float* __restrict__ pos) {
    __shared__ float w[MM];
    __shared__ float red[128];
    int bk = blockIdx.x, tid = threadIdx.x;
    if (tid == 0) {
        float mx = -3.4e38f;
        for (int m = 0; m < MM; m++) mx = fmaxf(mx, g_logits[bk * MM + m]);
        float ssum = 0.f;
        for (int m = 0; m < MM; m++) { float e = expf(g_logits[bk * MM + m] - mx); w[m] = e; ssum += e; }
        float inv = 1.0f / ssum;
        for (int m = 0; m < MM; m++) w[m] *= inv;
    }
    __syncthreads();
    if (tid < MM) g_w[bk * MM + tid] = w[tid];
    if (tid < RR) {
        float lo = 0.f;
        for (int m = 0; m < MM; m++) lo += w[m] * g_ua[(size_t)(bk * MM + m) * RR + tid];
        g_low[bk * RR + tid] = lo;
    }
    float p = g_apos[bk];
    float z = 0.f;
    for (int s = tid; s < SS; s += 128) {
        float d = fabsf(pos[s] - p);
        if (d <= 8.0f) z += expf(-d * 0.125f);
    }
    red[tid] = z;
    __syncthreads();
    for (int o = 64; o; o >>= 1) { if (tid < o) red[tid] += red[tid + o]; __syncthreads(); }
    if (tid == 0) g_Z[bk] = red[0];
}

// ---------------- K4: per (b,k,m): partial translated (deterministic, no atomics) ----------------
__global__ void __launch_bounds__(128) k_translate(const float* __restrict__ tb) {
    __shared__ float low[RR];
    __shared__ float wv;
    int id = blockIdx.x;
    int m = id % MM, bk = id / MM;
    int tid = threadIdx.x;
    if (tid < RR) low[tid] = g_low[bk * RR + tid];
    if (tid == 0) wv = g_w[bk * MM + m];
    __syncthreads();
    float wloc = wv;
    const float4* base = (const float4*)(tb + (size_t)m * DD * RR);
#pragma unroll
    for (int j = 0; j < 8; j++) {
        int d = tid + 128 * j;
        const float4* rp = base + (size_t)d * (RR / 4);
        float acc = 0.f;
#pragma unroll
        for (int i = 0; i < 16; i++) {
            float4 v = rp[i];
            acc += low[4 * i] * v.x + low[4 * i + 1] * v.y + low[4 * i + 2] * v.z + low[4 * i + 3] * v.w;
        }
        g_transp[(size_t)id * DD + d] = wloc * acc;
    }
}

__global__ void __launch_bounds__(256) k_tcombine() {
    int bk = blockIdx.x, tid = threadIdx.x;
    for (int d = tid; d < DD; d += 256) {
        float s = 0.f;
        for (int m = 0; m < MM; m++) s += g_transp[(size_t)(bk * MM + m) * DD + d];
        g_trans[bk * DD + d] = s;
    }
}

// ---------------- block reduce helper ----------------
__device__ __forceinline__ float2 bred2(float2 v, float* red) {
    int tid = threadIdx.x;
#pragma unroll
    for (int o = 16; o; o >>= 1) {
        v.x += __shfl_down_sync(0xffffffffu, v.x, o);
        v.y += __shfl_down_sync(0xffffffffu, v.y, o);
    }
    if ((tid & 31) == 0) { red[tid >> 5] = v.x; red[8 + (tid >> 5)] = v.y; }
    __syncthreads();
    if (tid == 0) {
        float a = 0.f, b = 0.f;
        for (int i = 0; i < 8; i++) { a += red[i]; b += red[8 + i]; }
        red[0] = a; red[8] = b;
    }
    __syncthreads();
    float2 r = make_float2(red[0], red[8]);
    __syncthreads();
    return r;
}

// ---------------- K5: fused row kernel (anchor update + 3 LNs + gate) ----------------
__global__ void __launch_bounds__(256) k_rows(
    const float* __restrict__ ts, const float* __restrict__ pt,
    const float* __restrict__ pos, const float* __restrict__ stab,
    const float* __restrict__ og, const float* __restrict__ ob,
    const float* __restrict__ tg, const float* __restrict__ tb2,
    const float* __restrict__ pg, const float* __restrict__ pb) {
    __shared__ float red[16];
    int row = blockIdx.x;
    int b = row / SS, s = row % SS;
    int tid = threadIdx.x;
    size_t base = (size_t)row * DD;
    float4 tsv = ((const float4*)(ts + base))[tid];
    float4 ptv = ((const float4*)(pt + base))[tid];
    float ps = pos[s];
    float4 upd = make_float4(0.f, 0.f, 0.f, 0.f);
#pragma unroll
    for (int k = 0; k < KA; k++) {
        int bk = b * KA + k;
        float dist = fabsf(ps - g_apos[bk]);
        if (dist <= 8.0f) {
            float c = expf(-dist * 0.125f) / g_Z[bk];
            float4 t = ((const float4*)(g_trans + (size_t)bk * DD))[tid];
            upd.x += c * t.x; upd.y += c * t.y; upd.z += c * t.z; upd.w += c * t.w;
        }
    }
    float4 x = make_float4(tsv.x + upd.x, tsv.y + upd.y, tsv.z + upd.z, tsv.w + upd.w);
    const float invD = 1.0f / DD;
    // LN1 (out_norm)
    float2 s1 = bred2(make_float2(x.x + x.y + x.z + x.w,
                                  x.x * x.x + x.y * x.y + x.z * x.z + x.w * x.w), red);
    float mu = s1.x * invD;
    float var = s1.y * invD - mu * mu;
    float rs = rsqrtf(var + 1e-5f);
    float4 gv = ((const float4*)og)[tid], bv = ((const float4*)ob)[tid];
    float4 aug;
    aug.x = (x.x - mu) * rs * gv.x + bv.x;
    aug.y = (x.y - mu) * rs * gv.y + bv.y;
    aug.z = (x.z - mu) * rs * gv.z + bv.z;
    aug.w = (x.w - mu) * rs * gv.w + bv.w;
    ((float4*)(g_tsaug + base))[tid] = aug;
    // LN2 (ts_norm)
    float2 s2 = bred2(make_float2(aug.x + aug.y + aug.z + aug.w,
                                  aug.x * aug.x + aug.y * aug.y + aug.z * aug.z + aug.w * aug.w), red);
    float mu2 = s2.x * invD;
    float rs2 = rsqrtf(s2.y * invD - mu2 * mu2 + 1e-5f);
    float4 gv2 = ((const float4*)tg)[tid], bv2 = ((const float4*)tb2)[tid];
    float4 tn;
    tn.x = (aug.x - mu2) * rs2 * gv2.x + bv2.x;
    tn.y = (aug.y - mu2) * rs2 * gv2.y + bv2.y;
    tn.z = (aug.z - mu2) * rs2 * gv2.z + bv2.z;
    tn.w = (aug.w - mu2) * rs2 * gv2.w + bv2.w;
    ((float4*)(g_tsn + base))[tid] = tn;
    // pt LN
    float2 s3 = bred2(make_float2(ptv.x + ptv.y + ptv.z + ptv.w,
                                  ptv.x * ptv.x + ptv.y * ptv.y + ptv.z * ptv.z + ptv.w * ptv.w), red);
    float mu3 = s3.x * invD;
    float rs3 = rsqrtf(s3.y * invD - mu3 * mu3 + 1e-5f);
    float4 gv3 = ((const float4*)pg)[tid], bv3 = ((const float4*)pb)[tid];
    float4 pn;
    pn.x = (ptv.x - mu3) * rs3 * gv3.x + bv3.x;
    pn.y = (ptv.y - mu3) * rs3 * gv3.y + bv3.y;
    pn.z = (ptv.z - mu3) * rs3 * gv3.z + bv3.z;
    pn.w = (ptv.w - mu3) * rs3 * gv3.w + bv3.w;
    ((float4*)(g_ptn + base))[tid] = pn;
    // cosine / gate
    float2 s4 = bred2(make_float2(tn.x * pn.x + tn.y * pn.y + tn.z * pn.z + tn.w * pn.w,
                                  tn.x * tn.x + tn.y * tn.y + tn.z * tn.z + tn.w * tn.w), red);
    float2 s5 = bred2(make_float2(pn.x * pn.x + pn.y * pn.y + pn.z * pn.z + pn.w * pn.w, 0.f), red);
    if (tid == 0) {
        float cosv = s4.x / (fmaxf(sqrtf(s4.y), 1e-6f) * fmaxf(sqrtf(s5.x), 1e-6f));
        float ag = 0.5f * (1.0f + cosv);
        float z = (ag - 0.72f) / 0.2f;
        float focus = 0.2f + 0.8f * expf(-0.5f * z * z);
        g_gate[row] = ag * focus * stab[row];
    }
}

// ---------------- K7: causal pool + form bf16 GEMM inputs ----------------
__global__ void __launch_bounds__(256) k_pool() {
    int row = blockIdx.x;
    int b = row / SS, s = row % SS;
    int tid = threadIdx.x;
    size_t base = (size_t)row * DD;
    int s1 = s - 1; if (s1 < 0) s1 = 0;
    int s2 = s - 2; if (s2 < 0) s2 = 0;
    size_t b1 = ((size_t)b * SS + s1) * DD;
    size_t b2 = ((size_t)b * SS + s2) * DD;
    float4 x0 = ((const float4*)(g_shared + base))[tid];
    float4 x1 = ((const float4*)(g_shared + b1))[tid];
    float4 x2 = ((const float4*)(g_shared + b2))[tid];
    float4 pl;
    pl.x = (x0.x + x1.x + x2.x) / 3.0f;
    pl.y = (x0.y + x1.y + x2.y) / 3.0f;
    pl.z = (x0.z + x1.z + x2.z) / 3.0f;
    pl.w = (x0.w + x1.w + x2.w) / 3.0f;
    float4 tn = ((const float4*)(g_tsn + base))[tid];
    float4 pn = ((const float4*)(g_ptn + base))[tid];
    __nv_bfloat162* o2 = (__nv_bfloat162*)(g_a2 + base) + tid * 2;
    o2[0] = __floats2bfloat162_rn(pl.x - tn.x, pl.y - tn.y);
    o2[1] = __floats2bfloat162_rn(pl.z - tn.z, pl.w - tn.w);
    __nv_bfloat162* o3 = (__nv_bfloat162*)(g_a3 + base) + tid * 2;
    o3[0] = __floats2bfloat162_rn(pl.x - pn.x, pl.y - pn.y);
    o3[1] = __floats2bfloat162_rn(pl.z - pn.z, pl.w - pn.w);
}

// ---------------- K6/K8/K9: WMMA bf16 GEMM, 128x128x32 tiles, fused epilogues ----------------
// MODE 1: shared = [tsn|ptn] @ W[0:2048] + bias + gate*W[2048]   (K=2048)
// MODE 2: ts_out = ts_aug + lb * (a2 @ ts_up_W)                   (K=1024)
// MODE 3: pt_out = pt_hidden + lb * (a3 @ pt_up_W)                (K=1024)
template<int MODE>
__global__ void __launch_bounds__(256) k_gemm(const float* __restrict__ W,
                                              const float* __restrict__ bias,
                                              const float* __restrict__ wlast,
                                              const float* __restrict__ basept,
                                              const float* __restrict__ bscale,
                                              float* __restrict__ outp, int Ktot) {
    extern __shared__ char smem_raw[];
    __nv_bfloat16* As = (__nv_bfloat16*)smem_raw;   // [128][40]
    __nv_bfloat16* Bs = As + 128 * 40;              // [32][136]
    float* Cs = (float*)smem_raw;                   // [128][132] epilogue reuse

    const int tid = threadIdx.x;
    const int bn = blockIdx.x;     // 0..7
    const int bm = blockIdx.y;     // 0..255
    const int row0 = bm * 128, col0 = bn * 128;
    const int wid = tid >> 5, wm = wid & 3, wn = wid >> 2;

    wmma::fragment<wmma::accumulator, 16, 16, 16, float> acc[2][4];
#pragma unroll
    for (int i = 0; i < 2; i++)
#pragma unroll
        for (int j = 0; j < 4; j++) wmma::fill_fragment(acc[i][j], 0.0f);

    const int ar = tid >> 3, ac = (tid & 7) * 4;
    const int br = tid >> 5, bc = (tid & 31) * 4;

    for (int kt = 0; kt < Ktot; kt += 32) {
#pragma unroll
        for (int p = 0; p < 4; p++) {
            int rr = ar + 32 * p;
            size_t grow = (size_t)(row0 + rr);
            int gk = kt + ac;
            __nv_bfloat16* dst = As + rr * 40 + ac;
            if (MODE == 1) {
                const float* src = (gk < DD) ? (g_tsn + grow * DD + gk)
                                             : (g_ptn + grow * DD + (gk - DD));
                float4 v = *(const float4*)src;
                *(__nv_bfloat162*)dst       = __floats2bfloat162_rn(v.x, v.y);
                *(__nv_bfloat162*)(dst + 2) = __floats2bfloat162_rn(v.z, v.w);
            } else {
                const __nv_bfloat16* src = (MODE == 2 ? g_a2 : g_a3) + grow * DD + gk;
                *(uint2*)dst = *(const uint2*)src;
            }
        }
#pragma unroll
        for (int p = 0; p < 4; p++) {
            int rr = br + 8 * p;
            int gk = kt + rr;
            float4 v = *(const float4*)(W + (size_t)gk * DD + col0 + bc);
            __nv_bfloat16* dst = Bs + rr * 136 + bc;
            *(__nv_bfloat162*)dst       = __floats2bfloat162_rn(v.x, v.y);
            *(__nv_bfloat162*)(dst + 2) = __floats2bfloat162_rn(v.z, v.w);
        }
        __syncthreads();
#pragma unroll
        for (int kk = 0; kk < 32; kk += 16) {
            wmma::fragment<wmma::matrix_a, 16, 16, 16, __nv_bfloat16, wmma::row_major> af[2];
            wmma::fragment<wmma::matrix_b, 16, 16, 16, __nv_bfloat16, wmma::row_major> bf[4];
#pragma unroll
            for (int i = 0; i < 2; i++) wmma::load_matrix_sync(af[i], As + (wm * 32 + i * 16) * 40 + kk, 40);
#pragma unroll
            for (int j = 0; j < 4; j++) wmma::load_matrix_sync(bf[j], Bs + kk * 136 + wn * 64 + j * 16, 136);
#pragma unroll
            for (int i = 0; i < 2; i++)
#pragma unroll
                for (int j = 0; j < 4; j++) wmma::mma_sync(acc[i][j], af[i], bf[j], acc[i][j]);
        }
        __syncthreads();
    }
#pragma unroll
    for (int i = 0; i < 2; i++)
#pragma unroll
        for (int j = 0; j < 4; j++)
            wmma::store_matrix_sync(Cs + (wm * 32 + i * 16) * 132 + wn * 64 + j * 16,
                                    acc[i][j], 132, wmma::mem_row_major);
    __syncthreads();
    float blend = 0.0f;
    if (MODE != 1) blend = 0.35f / (1.0f + expf(-bscale[0]));
    for (int e = tid; e < 128 * 128; e += 256) {
        int r = e >> 7, c = e & 127;
        size_t grow = (size_t)(row0 + r);
        int gcol = col0 + c;
        float v = Cs[r * 132 + c];
        if (MODE == 1) {
            v += bias[gcol] + g_gate[grow] * wlast[gcol];
            g_shared[grow * DD + gcol] = v;
        } else if (MODE == 2) {
            float lb = blend * g_gate[grow];
            outp[grow * DD + gcol] = g_tsaug[grow * DD + gcol] + lb * v;
        } else {
            float lb = blend * g_gate[grow];
            outp[grow * DD + gcol] = basept[grow * DD + gcol] + lb * v;
        }
    }
}

// ---------------- launch ----------------
extern "C" void kernel_launch(void* const* d_in, const int* in_sizes, int n_in,
                              void* d_out, int out_size) {
    const float* pt   = (const float*)d_in[0];
    const float* ts   = (const float*)d_in[1];
    const float* pos  = (const float*)d_in[2];
    const float* cent = (const float*)d_in[3];
    const float* stab = (const float*)d_in[4];
    const float* aw   = (const float*)d_in[5];
    const float* ab   = (const float*)d_in[6];
    const float* ta   = (const float*)d_in[7];
    const float* tb   = (const float*)d_in[8];
    const float* og   = (const float*)d_in[9];
    const float* ob   = (const float*)d_in[10];
    const float* tg   = (const float*)d_in[11];
    const float* tb2  = (const float*)d_in[12];
    const float* pg   = (const float*)d_in[13];
    const float* pb   = (const float*)d_in[14];
    const float* sW   = (const float*)d_in[15];
    const float* sb   = (const float*)d_in[16];
    const float* tuW  = (const float*)d_in[17];
    const float* puW  = (const float*)d_in[18];
    const float* bs   = (const float*)d_in[19];
    float* out = (float*)d_out;

    const int GEMM_SMEM = 128 * 132 * 4;  // 67584 B
    cudaFuncSetAttribute(k_gemm<1>, cudaFuncAttributeMaxDynamicSharedMemorySize, GEMM_SMEM);
    cudaFuncSetAttribute(k_gemm<2>, cudaFuncAttributeMaxDynamicSharedMemorySize, GEMM_SMEM);
    cudaFuncSetAttribute(k_gemm<3>, cudaFuncAttributeMaxDynamicSharedMemorySize, GEMM_SMEM);

    k_scores<<<NROWS / 8, 256>>>(pt, aw, ab);
    k_top3<<<BB, 256>>>(pos);
    k_basis<<<BB * KA * MM, 128>>>(pt, cent, ta);
    k_mix<<<BB * KA, 128>>>(pos);
    k_translate<<<BB * KA * MM, 128>>>(tb);
    k_tcombine<<<BB * KA, 256>>>();
    k_rows<<<NROWS, 256>>>(ts, pt, pos, stab, og, ob, tg, tb2, pg, pb);

    dim3 gg(8, 256);
    k_gemm<1><<<gg, 256, GEMM_SMEM>>>(sW, sb, sW + (size_t)2048 * DD, nullptr, nullptr, nullptr, 2048);
    k_pool<<<NROWS, 256>>>();
    k_gemm<2><<<gg, 256, GEMM_SMEM>>>(tuW, nullptr, nullptr, nullptr, bs, out, 1024);
    k_gemm<3><<<gg, 256, GEMM_SMEM>>>(puW, nullptr, nullptr, pt, bs, out + (size_t)NROWS * DD, 1024);
}

// round 5
// speedup vs baseline: 1.0016x; 1.0007x over previous
#include <cuda_runtime.h>
#include <cuda_bf16.h>
#include <mma.h>
using namespace nvcuda;

#define BB 8
#define SS 4096
#define DD 1024
#define MM 32
#define KA 3
#define RR 64
#define NROWS (BB*SS)

// ---------------- scratch (device globals; no allocations allowed) ----------------
__device__ float g_scores[NROWS];
__device__ int   g_aidx[BB*KA];
__device__ float g_apos[BB*KA];
__device__ float g_logits[BB*KA*MM];
__device__ float g_ua[BB*KA*MM*RR];
__device__ float g_w[BB*KA*MM];
__device__ float g_low[BB*KA*RR];
__device__ float g_Z[BB*KA];
__device__ float g_transp[BB*KA*MM*DD];
__device__ float g_trans[BB*KA*DD];
__device__ float g_tsaug[(size_t)NROWS*DD];
__device__ float g_tsn[(size_t)NROWS*DD];
__device__ float g_ptn[(size_t)NROWS*DD];
__device__ float g_gate[NROWS];
__device__ float g_shared[(size_t)NROWS*DD];
__device__ __nv_bfloat16 g_a2[(size_t)NROWS*DD];
__device__ __nv_bfloat16 g_a3[(size_t)NROWS*DD];

// ---------------- K0: anchor scores ----------------
__global__ void __launch_bounds__(256) k_scores(const float* __restrict__ pt,
                                                const float* __restrict__ aw,
                                                const float* __restrict__ ab) {
    int gw = (blockIdx.x * blockDim.x + threadIdx.x) >> 5;
    int lane = threadIdx.x & 31;
    if (gw >= NROWS) return;
    const float4* p = (const float4*)(pt + (size_t)gw * DD);
    const float4* w = (const float4*)aw;
    float s = 0.f;
#pragma unroll
    for (int i = 0; i < 8; i++) {
        float4 a = p[lane + 32 * i];
        float4 b = w[lane + 32 * i];
        s += a.x * b.x + a.y * b.y + a.z * b.z + a.w * b.w;
    }
#pragma unroll
    for (int o = 16; o; o >>= 1) s += __shfl_down_sync(0xffffffffu, s, o);
    if (!lane) g_scores[gw] = s + ab[0];
}

// ---------------- K1: top-3 per batch (jax top_k tie-break: lower index wins) ----------------
__global__ void k_top3(const float* __restrict__ pos) {
    __shared__ float sv[256];
    __shared__ int   si[256];
    __shared__ int   chosen[KA];
    int b = blockIdx.x, tid = threadIdx.x;
    const float* sc = g_scores + b * SS;
    for (int k = 0; k < KA; k++) {
        float bv = -3.4e38f; int bi = SS;
        for (int s = tid; s < SS; s += 256) {
            bool used = false;
            for (int j = 0; j < k; j++) used |= (chosen[j] == s);
            if (used) continue;
            float v = sc[s];
            if (v > bv || (v == bv && s < bi)) { bv = v; bi = s; }
        }
        sv[tid] = bv; si[tid] = bi;
        __syncthreads();
        for (int o = 128; o; o >>= 1) {
            if (tid < o) {
                if (sv[tid + o] > sv[tid] || (sv[tid + o] == sv[tid] && si[tid + o] < si[tid])) {
                    sv[tid] = sv[tid + o]; si[tid] = si[tid + o];
                }
            }
            __syncthreads();
        }
        if (tid == 0) {
            chosen[k] = si[0];
            g_aidx[b * KA + k] = si[0];
            g_apos[b * KA + k] = pos[si[0]];
        }
        __syncthreads();
    }
}

// ---------------- K2: per (b,k,m): cosine logit + u_a[r] = sum_d av[d]*trans_a[m,d,r] ----------------
__global__ void __launch_bounds__(128) k_basis(const float* __restrict__ pt,
                                               const float* __restrict__ cent,
                                               const float* __restrict__ ta) {
    __shared__ float av[DD];
    __shared__ float r1[128], r2[128], r3[128];
    int id = blockIdx.x;
    int m = id % MM, bk = id / MM;
    int b = bk / KA;
    int tid = threadIdx.x;
    const float* prow = pt + ((size_t)b * SS + g_aidx[bk]) * DD;
    const float* crow = cent + (size_t)m * DD;
    float pa = 0.f, pc = 0.f, pd = 0.f;
    for (int d = tid; d < DD; d += 128) {
        float a = prow[d], c = crow[d];
        av[d] = a; pa += a * a; pc += c * c; pd += a * c;
    }
    r1[tid] = pa; r2[tid] = pc; r3[tid] = pd;
    __syncthreads();
    for (int o = 64; o; o >>= 1) {
        if (tid < o) { r1[tid] += r1[tid + o]; r2[tid] += r2[tid + o]; r3[tid] += r3[tid + o]; }
        __syncthreads();
    }
    if (tid == 0) {
        float na = sqrtf(r1[0]), nc = sqrtf(r2[0]);
        g_logits[id] = r3[0] / (fmaxf(na, 1e-6f) * fmaxf(nc, 1e-6f));
    }
    __syncthreads();
    int r = tid & 63, h = tid >> 6;
    const float* tap = ta + (size_t)m * DD * RR + r;
    float u = 0.f;
    int d0 = h * 512;
#pragma unroll 8
    for (int d = d0; d < d0 + 512; d++) u += av[d] * tap[(size_t)d * RR];
    r1[tid] = u;
    __syncthreads();
    if (h == 0) g_ua[(size_t)id * RR + r] = r1[r] + r1[r + 64];
}

// ---------------- K3: per (b,k): softmax over modes, low[r], spread normalizer Z ----------------
__global__ void __launch_bounds__(128) k_mix(const float* __restrict__ pos) {
    __shared__ float w[MM];
    __shared__ float red[128];
    int bk = blockIdx.x, tid = threadIdx.x;
    if (tid == 0) {
        float mx = -3.4e38f;
        for (int m = 0; m < MM; m++) mx = fmaxf(mx, g_logits[bk * MM + m]);
        float ssum = 0.f;
        for (int m = 0; m < MM; m++) { float e = expf(g_logits[bk * MM + m] - mx); w[m] = e; ssum += e; }
        float inv = 1.0f / ssum;
        for (int m = 0; m < MM; m++) w[m] *= inv;
    }
    __syncthreads();
    if (tid < MM) g_w[bk * MM + tid] = w[tid];
    if (tid < RR) {
        float lo = 0.f;
        for (int m = 0; m < MM; m++) lo += w[m] * g_ua[(size_t)(bk * MM + m) * RR + tid];
        g_low[bk * RR + tid] = lo;
    }
    float p = g_apos[bk];
    float z = 0.f;
    for (int s = tid; s < SS; s += 128) {
        float d = fabsf(pos[s] - p);
        if (d <= 8.0f) z += expf(-d * 0.125f);
    }
    red[tid] = z;
    __syncthreads();
    for (int o = 64; o; o >>= 1) { if (tid < o) red[tid] += red[tid + o]; __syncthreads(); }
    if (tid == 0) g_Z[bk] = red[0];
}

// ---------------- K4: per (b,k,m): partial translated (deterministic, no atomics) ----------------
__global__ void __launch_bounds__(128) k_translate(const float* __restrict__ tb) {
    __shared__ float low[RR];
    __shared__ float wv;
    int id = blockIdx.x;
    int m = id % MM, bk = id / MM;
    int tid = threadIdx.x;
    if (tid < RR) low[tid] = g_low[bk * RR + tid];
    if (tid == 0) wv = g_w[bk * MM + m];
    __syncthreads();
    float wloc = wv;
    const float4* base = (const float4*)(tb + (size_t)m * DD * RR);
#pragma unroll
    for (int j = 0; j < 8; j++) {
        int d = tid + 128 * j;
        const float4* rp = base + (size_t)d * (RR / 4);
        float acc = 0.f;
#pragma unroll
        for (int i = 0; i < 16; i++) {
            float4 v = rp[i];
            acc += low[4 * i] * v.x + low[4 * i + 1] * v.y + low[4 * i + 2] * v.z + low[4 * i + 3] * v.w;
        }
        g_transp[(size_t)id * DD + d] = wloc * acc;
    }
}

__global__ void __launch_bounds__(256) k_tcombine() {
    int bk = blockIdx.x, tid = threadIdx.x;
    for (int d = tid; d < DD; d += 256) {
        float s = 0.f;
        for (int m = 0; m < MM; m++) s += g_transp[(size_t)(bk * MM + m) * DD + d];
        g_trans[bk * DD + d] = s;
    }
}

// ---------------- block reduce helper ----------------
__device__ __forceinline__ float2 bred2(float2 v, float* red) {
    int tid = threadIdx.x;
#pragma unroll
    for (int o = 16; o; o >>= 1) {
        v.x += __shfl_down_sync(0xffffffffu, v.x, o);
        v.y += __shfl_down_sync(0xffffffffu, v.y, o);
    }
    if ((tid & 31) == 0) { red[tid >> 5] = v.x; red[8 + (tid >> 5)] = v.y; }
    __syncthreads();
    if (tid == 0) {
        float a = 0.f, b = 0.f;
        for (int i = 0; i < 8; i++) { a += red[i]; b += red[8 + i]; }
        red[0] = a; red[8] = b;
    }
    __syncthreads();
    float2 r = make_float2(red[0], red[8]);
    __syncthreads();
    return r;
}

// ---------------- K5: fused row kernel (anchor update + 3 LNs + gate) ----------------
__global__ void __launch_bounds__(256) k_rows(
    const float* __restrict__ ts, const float* __restrict__ pt,
    const float* __restrict__ pos, const float* __restrict__ stab,
    const float* __restrict__ og, const float* __restrict__ ob,
    const float* __restrict__ tg, const float* __restrict__ tb2,
    const float* __restrict__ pg, const float* __restrict__ pb) {
    __shared__ float red[16];
    int row = blockIdx.x;
    int b = row / SS, s = row % SS;
    int tid = threadIdx.x;
    size_t base = (size_t)row * DD;
    float4 tsv = ((const float4*)(ts + base))[tid];
    float4 ptv = ((const float4*)(pt + base))[tid];
    float ps = pos[s];
    float4 upd = make_float4(0.f, 0.f, 0.f, 0.f);
#pragma unroll
    for (int k = 0; k < KA; k++) {
        int bk = b * KA + k;
        float dist = fabsf(ps - g_apos[bk]);
        if (dist <= 8.0f) {
            float c = expf(-dist * 0.125f) / g_Z[bk];
            float4 t = ((const float4*)(g_trans + (size_t)bk * DD))[tid];
            upd.x += c * t.x; upd.y += c * t.y; upd.z += c * t.z; upd.w += c * t.w;
        }
    }
    float4 x = make_float4(tsv.x + upd.x, tsv.y + upd.y, tsv.z + upd.z, tsv.w + upd.w);
    const float invD = 1.0f / DD;
    // LN1 (out_norm)
    float2 s1 = bred2(make_float2(x.x + x.y + x.z + x.w,
                                  x.x * x.x + x.y * x.y + x.z * x.z + x.w * x.w), red);
    float mu = s1.x * invD;
    float var = s1.y * invD - mu * mu;
    float rs = rsqrtf(var + 1e-5f);
    float4 gv = ((const float4*)og)[tid], bv = ((const float4*)ob)[tid];
    float4 aug;
    aug.x = (x.x - mu) * rs * gv.x + bv.x;
    aug.y = (x.y - mu) * rs * gv.y + bv.y;
    aug.z = (x.z - mu) * rs * gv.z + bv.z;
    aug.w = (x.w - mu) * rs * gv.w + bv.w;
    ((float4*)(g_tsaug + base))[tid] = aug;
    // LN2 (ts_norm)
    float2 s2 = bred2(make_float2(aug.x + aug.y + aug.z + aug.w,
                                  aug.x * aug.x + aug.y * aug.y + aug.z * aug.z + aug.w * aug.w), red);
    float mu2 = s2.x * invD;
    float rs2 = rsqrtf(s2.y * invD - mu2 * mu2 + 1e-5f);
    float4 gv2 = ((const float4*)tg)[tid], bv2 = ((const float4*)tb2)[tid];
    float4 tn;
    tn.x = (aug.x - mu2) * rs2 * gv2.x + bv2.x;
    tn.y = (aug.y - mu2) * rs2 * gv2.y + bv2.y;
    tn.z = (aug.z - mu2) * rs2 * gv2.z + bv2.z;
    tn.w = (aug.w - mu2) * rs2 * gv2.w + bv2.w;
    ((float4*)(g_tsn + base))[tid] = tn;
    // pt LN
    float2 s3 = bred2(make_float2(ptv.x + ptv.y + ptv.z + ptv.w,
                                  ptv.x * ptv.x + ptv.y * ptv.y + ptv.z * ptv.z + ptv.w * ptv.w), red);
    float mu3 = s3.x * invD;
    float rs3 = rsqrtf(s3.y * invD - mu3 * mu3 + 1e-5f);
    float4 gv3 = ((const float4*)pg)[tid], bv3 = ((const float4*)pb)[tid];
    float4 pn;
    pn.x = (ptv.x - mu3) * rs3 * gv3.x + bv3.x;
    pn.y = (ptv.y - mu3) * rs3 * gv3.y + bv3.y;
    pn.z = (ptv.z - mu3) * rs3 * gv3.z + bv3.z;
    pn.w = (ptv.w - mu3) * rs3 * gv3.w + bv3.w;
    ((float4*)(g_ptn + base))[tid] = pn;
    // cosine / gate
    float2 s4 = bred2(make_float2(tn.x * pn.x + tn.y * pn.y + tn.z * pn.z + tn.w * pn.w,
                                  tn.x * tn.x + tn.y * tn.y + tn.z * tn.z + tn.w * tn.w), red);
    float2 s5 = bred2(make_float2(pn.x * pn.x + pn.y * pn.y + pn.z * pn.z + pn.w * pn.w, 0.f), red);
    if (tid == 0) {
        float cosv = s4.x / (fmaxf(sqrtf(s4.y), 1e-6f) * fmaxf(sqrtf(s5.x), 1e-6f));
        float ag = 0.5f * (1.0f + cosv);
        float z = (ag - 0.72f) / 0.2f;
        float focus = 0.2f + 0.8f * expf(-0.5f * z * z);
        g_gate[row] = ag * focus * stab[row];
    }
}

// ---------------- K7: causal pool + form bf16 GEMM inputs ----------------
__global__ void __launch_bounds__(256) k_pool() {
    int row = blockIdx.x;
    int b = row / SS, s = row % SS;
    int tid = threadIdx.x;
    size_t base = (size_t)row * DD;
    int s1 = s - 1; if (s1 < 0) s1 = 0;
    int s2 = s - 2; if (s2 < 0) s2 = 0;
    size_t b1 = ((size_t)b * SS + s1) * DD;
    size_t b2 = ((size_t)b * SS + s2) * DD;
    float4 x0 = ((const float4*)(g_shared + base))[tid];
    float4 x1 = ((const float4*)(g_shared + b1))[tid];
    float4 x2 = ((const float4*)(g_shared + b2))[tid];
    float4 pl;
    pl.x = (x0.x + x1.x + x2.x) / 3.0f;
    pl.y = (x0.y + x1.y + x2.y) / 3.0f;
    pl.z = (x0.z + x1.z + x2.z) / 3.0f;
    pl.w = (x0.w + x1.w + x2.w) / 3.0f;
    float4 tn = ((const float4*)(g_tsn + base))[tid];
    float4 pn = ((const float4*)(g_ptn + base))[tid];
    __nv_bfloat162* o2 = (__nv_bfloat162*)(g_a2 + base) + tid * 2;
    o2[0] = __floats2bfloat162_rn(pl.x - tn.x, pl.y - tn.y);
    o2[1] = __floats2bfloat162_rn(pl.z - tn.z, pl.w - tn.w);
    __nv_bfloat162* o3 = (__nv_bfloat162*)(g_a3 + base) + tid * 2;
    o3[0] = __floats2bfloat162_rn(pl.x - pn.x, pl.y - pn.y);
    o3[1] = __floats2bfloat162_rn(pl.z - pn.z, pl.w - pn.w);
}

// ---------------- K6/K8/K9: WMMA bf16 GEMM, 128x128x32 tiles, fused epilogues ----------------
// MODE 1: shared = [tsn|ptn] @ W[0:2048] + bias + gate*W[2048]   (K=2048)
// MODE 2: ts_out = ts_aug + lb * (a2 @ ts_up_W)                   (K=1024)
// MODE 3: pt_out = pt_hidden + lb * (a3 @ pt_up_W)                (K=1024)
template<int MODE>
__global__ void __launch_bounds__(256) k_gemm(const float* __restrict__ W,
                                              const float* __restrict__ bias,
                                              const float* __restrict__ wlast,
                                              const float* __restrict__ basept,
                                              const float* __restrict__ bscale,
                                              float* __restrict__ outp, int Ktot) {
    extern __shared__ char smem_raw[];
    __nv_bfloat16* As = (__nv_bfloat16*)smem_raw;   // [128][40]
    __nv_bfloat16* Bs = As + 128 * 40;              // [32][136]
    float* Cs = (float*)smem_raw;                   // [128][132] epilogue reuse

    const int tid = threadIdx.x;
    const int bn = blockIdx.x;     // 0..7
    const int bm = blockIdx.y;     // 0..255
    const int row0 = bm * 128, col0 = bn * 128;
    const int wid = tid >> 5, wm = wid & 3, wn = wid >> 2;

    wmma::fragment<wmma::accumulator, 16, 16, 16, float> acc[2][4];
#pragma unroll
    for (int i = 0; i < 2; i++)
#pragma unroll
        for (int j = 0; j < 4; j++) wmma::fill_fragment(acc[i][j], 0.0f);

    const int ar = tid >> 3, ac = (tid & 7) * 4;
    const int br = tid >> 5, bc = (tid & 31) * 4;

    for (int kt = 0; kt < Ktot; kt += 32) {
#pragma unroll
        for (int p = 0; p < 4; p++) {
            int rr = ar + 32 * p;
            size_t grow = (size_t)(row0 + rr);
            int gk = kt + ac;
            __nv_bfloat16* dst = As + rr * 40 + ac;
            if (MODE == 1) {
                const float* src = (gk < DD) ? (g_tsn + grow * DD + gk)
                                             : (g_ptn + grow * DD + (gk - DD));
                float4 v = *(const float4*)src;
                *(__nv_bfloat162*)dst       = __floats2bfloat162_rn(v.x, v.y);
                *(__nv_bfloat162*)(dst + 2) = __floats2bfloat162_rn(v.z, v.w);
            } else {
                const __nv_bfloat16* src = (MODE == 2 ? g_a2 : g_a3) + grow * DD + gk;
                *(uint2*)dst = *(const uint2*)src;
            }
        }
#pragma unroll
        for (int p = 0; p < 4; p++) {
            int rr = br + 8 * p;
            int gk = kt + rr;
            float4 v = *(const float4*)(W + (size_t)gk * DD + col0 + bc);
            __nv_bfloat16* dst = Bs + rr * 136 + bc;
            *(__nv_bfloat162*)dst       = __floats2bfloat162_rn(v.x, v.y);
            *(__nv_bfloat162*)(dst + 2) = __floats2bfloat162_rn(v.z, v.w);
        }
        __syncthreads();
#pragma unroll
        for (int kk = 0; kk < 32; kk += 16) {
            wmma::fragment<wmma::matrix_a, 16, 16, 16, __nv_bfloat16, wmma::row_major> af[2];
            wmma::fragment<wmma::matrix_b, 16, 16, 16, __nv_bfloat16, wmma::row_major> bf[4];
#pragma unroll
            for (int i = 0; i < 2; i++) wmma::load_matrix_sync(af[i], As + (wm * 32 + i * 16) * 40 + kk, 40);
#pragma unroll
            for (int j = 0; j < 4; j++) wmma::load_matrix_sync(bf[j], Bs + kk * 136 + wn * 64 + j * 16, 136);
#pragma unroll
            for (int i = 0; i < 2; i++)
#pragma unroll
                for (int j = 0; j < 4; j++) wmma::mma_sync(acc[i][j], af[i], bf[j], acc[i][j]);
        }
        __syncthreads();
    }
#pragma unroll
    for (int i = 0; i < 2; i++)
#pragma unroll
        for (int j = 0; j < 4; j++)
            wmma::store_matrix_sync(Cs + (wm * 32 + i * 16) * 132 + wn * 64 + j * 16,
                                    acc[i][j], 132, wmma::mem_row_major);
    __syncthreads();
    float blend = 0.0f;
    if (MODE != 1) blend = 0.35f / (1.0f + expf(-bscale[0]));
    for (int e = tid; e < 128 * 128; e += 256) {
        int r = e >> 7, c = e & 127;
        size_t grow = (size_t)(row0 + r);
        int gcol = col0 + c;
        float v = Cs[r * 132 + c];
        if (MODE == 1) {
            v += bias[gcol] + g_gate[grow] * wlast[gcol];
            g_shared[grow * DD + gcol] = v;
        } else if (MODE == 2) {
            float lb = blend * g_gate[grow];
            outp[grow * DD + gcol] = g_tsaug[grow * DD + gcol] + lb * v;
        } else {
            float lb = blend * g_gate[grow];
            outp[grow * DD + gcol] = basept[grow * DD + gcol] + lb * v;
        }
    }
}

// ---------------- launch ----------------
extern "C" void kernel_launch(void* const* d_in, const int* in_sizes, int n_in,
                              void* d_out, int out_size) {
    const float* pt   = (const float*)d_in[0];
    const float* ts   = (const float*)d_in[1];
    const float* pos  = (const float*)d_in[2];
    const float* cent = (const float*)d_in[3];
    const float* stab = (const float*)d_in[4];
    const float* aw   = (const float*)d_in[5];
    const float* ab   = (const float*)d_in[6];
    const float* ta   = (const float*)d_in[7];
    const float* tb   = (const float*)d_in[8];
    const float* og   = (const float*)d_in[9];
    const float* ob   = (const float*)d_in[10];
    const float* tg   = (const float*)d_in[11];
    const float* tb2  = (const float*)d_in[12];
    const float* pg   = (const float*)d_in[13];
    const float* pb   = (const float*)d_in[14];
    const float* sW   = (const float*)d_in[15];
    const float* sb   = (const float*)d_in[16];
    const float* tuW  = (const float*)d_in[17];
    const float* puW  = (const float*)d_in[18];
    const float* bs   = (const float*)d_in[19];
    float* out = (float*)d_out;

    const int GEMM_SMEM = 128 * 132 * 4;  // 67584 B
    cudaFuncSetAttribute(k_gemm<1>, cudaFuncAttributeMaxDynamicSharedMemorySize, GEMM_SMEM);
    cudaFuncSetAttribute(k_gemm<2>, cudaFuncAttributeMaxDynamicSharedMemorySize, GEMM_SMEM);
    cudaFuncSetAttribute(k_gemm<3>, cudaFuncAttributeMaxDynamicSharedMemorySize, GEMM_SMEM);

    k_scores<<<NROWS / 8, 256>>>(pt, aw, ab);
    k_top3<<<BB, 256>>>(pos);
    k_basis<<<BB * KA * MM, 128>>>(pt, cent, ta);
    k_mix<<<BB * KA, 128>>>(pos);
    k_translate<<<BB * KA * MM, 128>>>(tb);
    k_tcombine<<<BB * KA, 256>>>();
    k_rows<<<NROWS, 256>>>(ts, pt, pos, stab, og, ob, tg, tb2, pg, pb);

    dim3 gg(8, 256);
    k_gemm<1><<<gg, 256, GEMM_SMEM>>>(sW, sb, sW + (size_t)2048 * DD, nullptr, nullptr, nullptr, 2048);
    k_pool<<<NROWS, 256>>>();
    k_gemm<2><<<gg, 256, GEMM_SMEM>>>(tuW, nullptr, nullptr, nullptr, bs, out, 1024);
    k_gemm<3><<<gg, 256, GEMM_SMEM>>>(puW, nullptr, nullptr, pt, bs, out + (size_t)NROWS * DD, 1024);
}

// round 8
// speedup vs baseline: 1.4932x; 1.4908x over previous
#include <cuda_runtime.h>
#include <cuda_bf16.h>
#include <mma.h>
#include <cstdint>
using namespace nvcuda;

#define BB 8
#define SS 4096
#define DD 1024
#define MM 32
#define KA 3
#define RR 64
#define NROWS (BB*SS)

// ---------------- scratch (device globals; no allocations allowed) ----------------
__device__ float g_scores[NROWS];
__device__ int   g_aidx[BB*KA];
__device__ float g_apos[BB*KA];
__device__ float g_logits[BB*KA*MM];
__device__ float g_ua[BB*KA*MM*RR];
__device__ float g_w[BB*KA*MM];
__device__ float g_low[BB*KA*RR];
__device__ float g_Z[BB*KA];
__device__ float g_transp[BB*KA*MM*DD];
__device__ float g_trans[BB*KA*DD];
__device__ float g_tsaug[(size_t)NROWS*DD];
__device__ float g_gate[NROWS];
__device__ float g_shared[(size_t)NROWS*DD];
__device__ __align__(16) __nv_bfloat16 g_cat[(size_t)NROWS*2*DD];   // [tsn|ptn] bf16
__device__ __align__(16) __nv_bfloat16 g_a2[(size_t)NROWS*DD];
__device__ __align__(16) __nv_bfloat16 g_a3[(size_t)NROWS*DD];
__device__ __align__(16) __nv_bfloat16 g_w1[(size_t)2048*DD];       // shared_W[0:2048] bf16
__device__ __align__(16) __nv_bfloat16 g_w2[(size_t)DD*DD];         // ts_up_W bf16
__device__ __align__(16) __nv_bfloat16 g_w3[(size_t)DD*DD];         // pt_up_W bf16

// ---------------- cp.async helpers ----------------
__device__ __forceinline__ void cp16(void* dst, const void* src) {
    unsigned int d = (unsigned int)__cvta_generic_to_shared(dst);
    asm volatile("cp.async.cg.shared.global [%0], [%1], 16;\n" :: "r"(d), "l"(src));
}
#define CP_COMMIT() asm volatile("cp.async.commit_group;\n" ::: "memory")
#define CP_WAIT1()  asm volatile("cp.async.wait_group 1;\n" ::: "memory")
#define CP_WAIT0()  asm volatile("cp.async.wait_group 0;\n" ::: "memory")

// ---------------- weight fp32 -> bf16 ----------------
__global__ void __launch_bounds__(256) k_cvt(const float* __restrict__ src,
                                             __nv_bfloat16* __restrict__ dst, int n4) {
    int i = blockIdx.x * blockDim.x + threadIdx.x;
    if (i >= n4) return;
    float4 v = ((const float4*)src)[i];
    __nv_bfloat162* o = (__nv_bfloat162*)dst + i * 2;
    o[0] = __floats2bfloat162_rn(v.x, v.y);
    o[1] = __floats2bfloat162_rn(v.z, v.w);
}

// ---------------- K0: anchor scores ----------------
__global__ void __launch_bounds__(256) k_scores(const float* __restrict__ pt,
                                                const float* __restrict__ aw,
                                                const float* __restrict__ ab) {
    int gw = (blockIdx.x * blockDim.x + threadIdx.x) >> 5;
    int lane = threadIdx.x & 31;
    if (gw >= NROWS) return;
    const float4* p = (const float4*)(pt + (size_t)gw * DD);
    const float4* w = (const float4*)aw;
    float s = 0.f;
#pragma unroll
    for (int i = 0; i < 8; i++) {
        float4 a = p[lane + 32 * i];
        float4 b = w[lane + 32 * i];
        s += a.x * b.x + a.y * b.y + a.z * b.z + a.w * b.w;
    }
#pragma unroll
    for (int o = 16; o; o >>= 1) s += __shfl_down_sync(0xffffffffu, s, o);
    if (!lane) g_scores[gw] = s + ab[0];
}

// ---------------- K1: top-3 per batch ----------------
__global__ void k_top3(const float* __restrict__ pos) {
    __shared__ float sv[256];
    __shared__ int   si[256];
    __shared__ int   chosen[KA];
    int b = blockIdx.x, tid = threadIdx.x;
    const float* sc = g_scores + b * SS;
    for (int k = 0; k < KA; k++) {
        float bv = -3.4e38f; int bi = SS;
        for (int s = tid; s < SS; s += 256) {
            bool used = false;
            for (int j = 0; j < k; j++) used |= (chosen[j] == s);
            if (used) continue;
            float v = sc[s];
            if (v > bv || (v == bv && s < bi)) { bv = v; bi = s; }
        }
        sv[tid] = bv; si[tid] = bi;
        __syncthreads();
        for (int o = 128; o; o >>= 1) {
            if (tid < o) {
                if (sv[tid + o] > sv[tid] || (sv[tid + o] == sv[tid] && si[tid + o] < si[tid])) {
                    sv[tid] = sv[tid + o]; si[tid] = si[tid + o];
                }
            }
            __syncthreads();
        }
        if (tid == 0) {
            chosen[k] = si[0];
            g_aidx[b * KA + k] = si[0];
            g_apos[b * KA + k] = pos[si[0]];
        }
        __syncthreads();
    }
}

// ---------------- K2: per (b,k,m): cosine logit + u_a ----------------
__global__ void __launch_bounds__(128) k_basis(const float* __restrict__ pt,
                                               const float* __restrict__ cent,
                                               const float* __restrict__ ta) {
    __shared__ float av[DD];
    __shared__ float r1[128], r2[128], r3[128];
    int id = blockIdx.x;
    int m = id % MM, bk = id / MM;
    int b = bk / KA;
    int tid = threadIdx.x;
    const float* prow = pt + ((size_t)b * SS + g_aidx[bk]) * DD;
    const float* crow = cent + (size_t)m * DD;
    float pa = 0.f, pc = 0.f, pd = 0.f;
    for (int d = tid; d < DD; d += 128) {
        float a = prow[d], c = crow[d];
        av[d] = a; pa += a * a; pc += c * c; pd += a * c;
    }
    r1[tid] = pa; r2[tid] = pc; r3[tid] = pd;
    __syncthreads();
    for (int o = 64; o; o >>= 1) {
        if (tid < o) { r1[tid] += r1[tid + o]; r2[tid] += r2[tid + o]; r3[tid] += r3[tid + o]; }
        __syncthreads();
    }
    if (tid == 0) {
        float na = sqrtf(r1[0]), nc = sqrtf(r2[0]);
        g_logits[id] = r3[0] / (fmaxf(na, 1e-6f) * fmaxf(nc, 1e-6f));
    }
    __syncthreads();
    int r = tid & 63, h = tid >> 6;
    const float* tap = ta + (size_t)m * DD * RR + r;
    float u = 0.f;
    int d0 = h * 512;
#pragma unroll 8
    for (int d = d0; d < d0 + 512; d++) u += av[d] * tap[(size_t)d * RR];
    r1[tid] = u;
    __syncthreads();
    if (h == 0) g_ua[(size_t)id * RR + r] = r1[r] + r1[r + 64];
}

// ---------------- K3: per (b,k): softmax, low, spread normalizer ----------------
__global__ void __launch_bounds__(128) k_mix(const float* __restrict__ pos) {
    __shared__ float w[MM];
    __shared__ float red[128];
    int bk = blockIdx.x, tid = threadIdx.x;
    if (tid == 0) {
        float mx = -3.4e38f;
        for (int m = 0; m < MM; m++) mx = fmaxf(mx, g_logits[bk * MM + m]);
        float ssum = 0.f;
        for (int m = 0; m < MM; m++) { float e = expf(g_logits[bk * MM + m] - mx); w[m] = e; ssum += e; }
        float inv = 1.0f / ssum;
        for (int m = 0; m < MM; m++) w[m] *= inv;
    }
    __syncthreads();
    if (tid < MM) g_w[bk * MM + tid] = w[tid];
    if (tid < RR) {
        float lo = 0.f;
        for (int m = 0; m < MM; m++) lo += w[m] * g_ua[(size_t)(bk * MM + m) * RR + tid];
        g_low[bk * RR + tid] = lo;
    }
    float p = g_apos[bk];
    float z = 0.f;
    for (int s = tid; s < SS; s += 128) {
        float d = fabsf(pos[s] - p);
        if (d <= 8.0f) z += expf(-d * 0.125f);
    }
    red[tid] = z;
    __syncthreads();
    for (int o = 64; o; o >>= 1) { if (tid < o) red[tid] += red[tid + o]; __syncthreads(); }
    if (tid == 0) g_Z[bk] = red[0];
}

// ---------------- K4: per (b,k,m): partial translated ----------------
__global__ void __launch_bounds__(128) k_translate(const float* __restrict__ tb) {
    __shared__ float low[RR];
    __shared__ float wv;
    int id = blockIdx.x;
    int m = id % MM, bk = id / MM;
    int tid = threadIdx.x;
    if (tid < RR) low[tid] = g_low[bk * RR + tid];
    if (tid == 0) wv = g_w[bk * MM + m];
    __syncthreads();
    float wloc = wv;
    const float4* base = (const float4*)(tb + (size_t)m * DD * RR);
#pragma unroll
    for (int j = 0; j < 8; j++) {
        int d = tid + 128 * j;
        const float4* rp = base + (size_t)d * (RR / 4);
        float acc = 0.f;
#pragma unroll
        for (int i = 0; i < 16; i++) {
            float4 v = rp[i];
            acc += low[4 * i] * v.x + low[4 * i + 1] * v.y + low[4 * i + 2] * v.z + low[4 * i + 3] * v.w;
        }
        g_transp[(size_t)id * DD + d] = wloc * acc;
    }
}

__global__ void __launch_bounds__(256) k_tcombine() {
    int bk = blockIdx.x, tid = threadIdx.x;
    for (int d = tid; d < DD; d += 256) {
        float s = 0.f;
        for (int m = 0; m < MM; m++) s += g_transp[(size_t)(bk * MM + m) * DD + d];
        g_trans[bk * DD + d] = s;
    }
}

// ---------------- block reduce helper ----------------
__device__ __forceinline__ float2 bred2(float2 v, float* red) {
    int tid = threadIdx.x;
#pragma unroll
    for (int o = 16; o; o >>= 1) {
        v.x += __shfl_down_sync(0xffffffffu, v.x, o);
        v.y += __shfl_down_sync(0xffffffffu, v.y, o);
    }
    if ((tid & 31) == 0) { red[tid >> 5] = v.x; red[8 + (tid >> 5)] = v.y; }
    __syncthreads();
    if (tid == 0) {
        float a = 0.f, b = 0.f;
        for (int i = 0; i < 8; i++) { a += red[i]; b += red[8 + i]; }
        red[0] = a; red[8] = b;
    }
    __syncthreads();
    float2 r = make_float2(red[0], red[8]);
    __syncthreads();
    return r;
}

// ---------------- K5: fused row kernel (anchor update + 3 LNs + gate) ----------------
__global__ void __launch_bounds__(256) k_rows(
    const float* __restrict__ ts, const float* __restrict__ pt,
    const float* __restrict__ pos, const float* __restrict__ stab,
    const float* __restrict__ og, const float* __restrict__ ob,
    const float* __restrict__ tg, const float* __restrict__ tb2,
    const float* __restrict__ pg, const float* __restrict__ pb) {
    __shared__ float red[16];
    int row = blockIdx.x;
    int b = row / SS, s = row % SS;
    int tid = threadIdx.x;
    size_t base = (size_t)row * DD;
    float4 tsv = ((const float4*)(ts + base))[tid];
    float4 ptv = ((const float4*)(pt + base))[tid];
    float ps = pos[s];
    float4 upd = make_float4(0.f, 0.f, 0.f, 0.f);
#pragma unroll
    for (int k = 0; k < KA; k++) {
        int bk = b * KA + k;
        float dist = fabsf(ps - g_apos[bk]);
        if (dist <= 8.0f) {
            float c = expf(-dist * 0.125f) / g_Z[bk];
            float4 t = ((const float4*)(g_trans + (size_t)bk * DD))[tid];
            upd.x += c * t.x; upd.y += c * t.y; upd.z += c * t.z; upd.w += c * t.w;
        }
    }
    float4 x = make_float4(tsv.x + upd.x, tsv.y + upd.y, tsv.z + upd.z, tsv.w + upd.w);
    const float invD = 1.0f / DD;
    // LN1 (out_norm)
    float2 s1 = bred2(make_float2(x.x + x.y + x.z + x.w,
                                  x.x * x.x + x.y * x.y + x.z * x.z + x.w * x.w), red);
    float mu = s1.x * invD;
    float var = s1.y * invD - mu * mu;
    float rs = rsqrtf(var + 1e-5f);
    float4 gv = ((const float4*)og)[tid], bv = ((const float4*)ob)[tid];
    float4 aug;
    aug.x = (x.x - mu) * rs * gv.x + bv.x;
    aug.y = (x.y - mu) * rs * gv.y + bv.y;
    aug.z = (x.z - mu) * rs * gv.z + bv.z;
    aug.w = (x.w - mu) * rs * gv.w + bv.w;
    ((float4*)(g_tsaug + base))[tid] = aug;
    // LN2 (ts_norm)
    float2 s2 = bred2(make_float2(aug.x + aug.y + aug.z + aug.w,
                                  aug.x * aug.x + aug.y * aug.y + aug.z * aug.z + aug.w * aug.w), red);
    float mu2 = s2.x * invD;
    float rs2 = rsqrtf(s2.y * invD - mu2 * mu2 + 1e-5f);
    float4 gv2 = ((const float4*)tg)[tid], bv2 = ((const float4*)tb2)[tid];
    float4 tn;
    tn.x = (aug.x - mu2) * rs2 * gv2.x + bv2.x;
    tn.y = (aug.y - mu2) * rs2 * gv2.y + bv2.y;
    tn.z = (aug.z - mu2) * rs2 * gv2.z + bv2.z;
    tn.w = (aug.w - mu2) * rs2 * gv2.w + bv2.w;
    // pt LN
    float2 s3 = bred2(make_float2(ptv.x + ptv.y + ptv.z + ptv.w,
                                  ptv.x * ptv.x + ptv.y * ptv.y + ptv.z * ptv.z + ptv.w * ptv.w), red);
    float mu3 = s3.x * invD;
    float rs3 = rsqrtf(s3.y * invD - mu3 * mu3 + 1e-5f);
    float4 gv3 = ((const float4*)pg)[tid], bv3 = ((const float4*)pb)[tid];
    float4 pn;
    pn.x = (ptv.x - mu3) * rs3 * gv3.x + bv3.x;
    pn.y = (ptv.y - mu3) * rs3 * gv3.y + bv3.y;
    pn.z = (ptv.z - mu3) * rs3 * gv3.z + bv3.z;
    pn.w = (ptv.w - mu3) * rs3 * gv3.w + bv3.w;
    // store tsn|ptn as bf16 (concatenated GEMM-A layout)
    {
        __nv_bfloat162* ct = (__nv_bfloat162*)(g_cat + (size_t)row * 2 * DD) + tid * 2;
        ct[0] = __floats2bfloat162_rn(tn.x, tn.y);
        ct[1] = __floats2bfloat162_rn(tn.z, tn.w);
        __nv_bfloat162* cp2 = (__nv_bfloat162*)(g_cat + (size_t)row * 2 * DD + DD) + tid * 2;
        cp2[0] = __floats2bfloat162_rn(pn.x, pn.y);
        cp2[1] = __floats2bfloat162_rn(pn.z, pn.w);
    }
    // cosine / gate
    float2 s4 = bred2(make_float2(tn.x * pn.x + tn.y * pn.y + tn.z * pn.z + tn.w * pn.w,
                                  tn.x * tn.x + tn.y * tn.y + tn.z * tn.z + tn.w * tn.w), red);
    float2 s5 = bred2(make_float2(pn.x * pn.x + pn.y * pn.y + pn.z * pn.z + pn.w * pn.w, 0.f), red);
    if (tid == 0) {
        float cosv = s4.x / (fmaxf(sqrtf(s4.y), 1e-6f) * fmaxf(sqrtf(s5.x), 1e-6f));
        float ag = 0.5f * (1.0f + cosv);
        float z = (ag - 0.72f) / 0.2f;
        float focus = 0.2f + 0.8f * expf(-0.5f * z * z);
        g_gate[row] = ag * focus * stab[row];
    }
}

// ---------------- K7: causal pool + form bf16 GEMM inputs ----------------
__global__ void __launch_bounds__(256) k_pool() {
    int row = blockIdx.x;
    int b = row / SS, s = row % SS;
    int tid = threadIdx.x;
    size_t base = (size_t)row * DD;
    int s1 = s - 1; if (s1 < 0) s1 = 0;
    int s2 = s - 2; if (s2 < 0) s2 = 0;
    size_t b1 = ((size_t)b * SS + s1) * DD;
    size_t b2 = ((size_t)b * SS + s2) * DD;
    float4 x0 = ((const float4*)(g_shared + base))[tid];
    float4 x1 = ((const float4*)(g_shared + b1))[tid];
    float4 x2 = ((const float4*)(g_shared + b2))[tid];
    float4 pl;
    pl.x = (x0.x + x1.x + x2.x) / 3.0f;
    pl.y = (x0.y + x1.y + x2.y) / 3.0f;
    pl.z = (x0.z + x1.z + x2.z) / 3.0f;
    pl.w = (x0.w + x1.w + x2.w) / 3.0f;
    const __nv_bfloat162* ct = (const __nv_bfloat162*)(g_cat + (size_t)row * 2 * DD) + tid * 2;
    const __nv_bfloat162* cp2 = (const __nv_bfloat162*)(g_cat + (size_t)row * 2 * DD + DD) + tid * 2;
    float2 t01 = __bfloat1622float2(ct[0]);
    float2 t23 = __bfloat1622float2(ct[1]);
    float2 p01 = __bfloat1622float2(cp2[0]);
    float2 p23 = __bfloat1622float2(cp2[1]);
    __nv_bfloat162* o2 = (__nv_bfloat162*)(g_a2 + base) + tid * 2;
    o2[0] = __floats2bfloat162_rn(pl.x - t01.x, pl.y - t01.y);
    o2[1] = __floats2bfloat162_rn(pl.z - t23.x, pl.w - t23.y);
    __nv_bfloat162* o3 = (__nv_bfloat162*)(g_a3 + base) + tid * 2;
    o3[0] = __floats2bfloat162_rn(pl.x - p01.x, pl.y - p01.y);
    o3[1] = __floats2bfloat162_rn(pl.z - p23.x, pl.w - p23.y);
}

// ---------------- pipelined bf16 WMMA GEMM, 128x128 tiles, BK=32, 3-stage cp.async ----------------
// MODE 1: shared = [tsn|ptn] @ W + bias + gate*wlast   (K=2048)
// MODE 2: ts_out = ts_aug + lb * (a2 @ ts_up_W)        (K=1024)
// MODE 3: pt_out = pt_hidden + lb * (a3 @ pt_up_W)     (K=1024)
#define ASTRIDE 40
#define BSTRIDE 136
#define A_ST_ELEMS (128*ASTRIDE)   // 5120
#define B_ST_ELEMS (32*BSTRIDE)    // 4352

template<int MODE>
__global__ void __launch_bounds__(256) k_gemm(const __nv_bfloat16* __restrict__ A, int lda,
                                              const __nv_bfloat16* __restrict__ Bw,
                                              const float* __restrict__ bias,
                                              const float* __restrict__ wlast,
                                              const float* __restrict__ basept,
                                              const float* __restrict__ bscale,
                                              float* __restrict__ outp, int Ktot) {
    extern __shared__ char smem_raw[];
    __nv_bfloat16* As = (__nv_bfloat16*)smem_raw;          // 3 stages x 128x40
    __nv_bfloat16* Bs = As + 3 * A_ST_ELEMS;               // 3 stages x 32x136
    float* Cs = (float*)smem_raw;                          // epilogue reuse: 128x132

    const int tid = threadIdx.x;
    const int bn = blockIdx.x;     // 0..7
    const int bm = blockIdx.y;     // 0..255
    const int row0 = bm * 128, col0 = bn * 128;
    const int wid = tid >> 5, wm = wid & 3, wn = wid >> 2;

    // load mapping: A 512 x 16B chunks (4/row), B 512 x 16B chunks (16/row)
    const int arow = tid >> 2, acc8 = (tid & 3) * 8;
    const int brow = tid >> 4, bcc8 = (tid & 15) * 8;

    wmma::fragment<wmma::accumulator, 16, 16, 16, float> acc[2][4];
#pragma unroll
    for (int i = 0; i < 2; i++)
#pragma unroll
        for (int j = 0; j < 4; j++) wmma::fill_fragment(acc[i][j], 0.0f);

    const int nIter = Ktot >> 5;

    // prologue: stages 0,1
#pragma unroll
    for (int st = 0; st < 2; st++) {
        int kt = st * 32;
        cp16(As + st * A_ST_ELEMS + arow * ASTRIDE + acc8,
             A + (size_t)(row0 + arow) * lda + kt + acc8);
        cp16(As + st * A_ST_ELEMS + (arow + 64) * ASTRIDE + acc8,
             A + (size_t)(row0 + arow + 64) * lda + kt + acc8);
        cp16(Bs + st * B_ST_ELEMS + brow * BSTRIDE + bcc8,
             Bw + (size_t)(kt + brow) * DD + col0 + bcc8);
        cp16(Bs + st * B_ST_ELEMS + (brow + 16) * BSTRIDE + bcc8,
             Bw + (size_t)(kt + brow + 16) * DD + col0 + bcc8);
        CP_COMMIT();
    }

    int st = 0;
    for (int it = 0; it < nIter; it++) {
        CP_WAIT1();
        __syncthreads();
        const __nv_bfloat16* Ab = As + st * A_ST_ELEMS;
        const __nv_bfloat16* Bb = Bs + st * B_ST_ELEMS;
#pragma unroll
        for (int kk = 0; kk < 32; kk += 16) {
            wmma::fragment<wmma::matrix_a, 16, 16, 16, __nv_bfloat16, wmma::row_major> af[2];
            wmma::fragment<wmma::matrix_b, 16, 16, 16, __nv_bfloat16, wmma::row_major> bf[4];
#pragma unroll
            for (int i = 0; i < 2; i++)
                wmma::load_matrix_sync(af[i], Ab + (wm * 32 + i * 16) * ASTRIDE + kk, ASTRIDE);
#pragma unroll
            for (int j = 0; j < 4; j++)
                wmma::load_matrix_sync(bf[j], Bb + kk * BSTRIDE + wn * 64 + j * 16, BSTRIDE);
#pragma unroll
            for (int i = 0; i < 2; i++)
#pragma unroll
                for (int j = 0; j < 4; j++) wmma::mma_sync(acc[i][j], af[i], bf[j], acc[i][j]);
        }
        int nf = it + 2;
        if (nf < nIter) {
            int ns = nf - (nf / 3) * 3;
            int kt = nf * 32;
            cp16(As + ns * A_ST_ELEMS + arow * ASTRIDE + acc8,
                 A + (size_t)(row0 + arow) * lda + kt + acc8);
            cp16(As + ns * A_ST_ELEMS + (arow + 64) * ASTRIDE + acc8,
                 A + (size_t)(row0 + arow + 64) * lda + kt + acc8);
            cp16(Bs + ns * B_ST_ELEMS + brow * BSTRIDE + bcc8,
                 Bw + (size_t)(kt + brow) * DD + col0 + bcc8);
            cp16(Bs + ns * B_ST_ELEMS + (brow + 16) * BSTRIDE + bcc8,
                 Bw + (size_t)(kt + brow + 16) * DD + col0 + bcc8);
        }
        CP_COMMIT();
        st++; if (st == 3) st = 0;
    }
    CP_WAIT0();
    __syncthreads();

#pragma unroll
    for (int i = 0; i < 2; i++)
#pragma unroll
        for (int j = 0; j < 4; j++)
            wmma::store_matrix_sync(Cs + (wm * 32 + i * 16) * 132 + wn * 64 + j * 16,
                                    acc[i][j], 132, wmma::mem_row_major);
    __syncthreads();
    float blend = 0.0f;
    if (MODE != 1) blend = 0.35f / (1.0f + expf(-bscale[0]));
    for (int e = tid; e < 32 * 128; e += 256) {      // 4096 float4 chunks
        int r = e >> 5, c4 = (e & 31) * 4;
        size_t grow = (size_t)(row0 + r);
        int gcol = col0 + c4;
        const float* cp = Cs + r * 132 + c4;
        float4 v = make_float4(cp[0], cp[1], cp[2], cp[3]);
        if (MODE == 1) {
            float gte = g_gate[grow];
            float4 bi = *(const float4*)(bias + gcol);
            float4 wl = *(const float4*)(wlast + gcol);
            v.x += bi.x + gte * wl.x; v.y += bi.y + gte * wl.y;
            v.z += bi.z + gte * wl.z; v.w += bi.w + gte * wl.w;
            *(float4*)(g_shared + grow * DD + gcol) = v;
        } else {
            float lb = blend * g_gate[grow];
            const float* bp = (MODE == 2 ? g_tsaug : basept) + grow * DD + gcol;
            float4 b4 = *(const float4*)bp;
            float4 o4 = make_float4(b4.x + lb * v.x, b4.y + lb * v.y,
                                    b4.z + lb * v.z, b4.w + lb * v.w);
            *(float4*)(outp + grow * DD + gcol) = o4;
        }
    }
}

// ---------------- launch ----------------
extern "C" void kernel_launch(void* const* d_in, const int* in_sizes, int n_in,
                              void* d_out, int out_size) {
    const float* pt   = (const float*)d_in[0];
    const float* ts   = (const float*)d_in[1];
    const float* pos  = (const float*)d_in[2];
    const float* cent = (const float*)d_in[3];
    const float* stab = (const float*)d_in[4];
    const float* aw   = (const float*)d_in[5];
    const float* ab   = (const float*)d_in[6];
    const float* ta   = (const float*)d_in[7];
    const float* tb   = (const float*)d_in[8];
    const float* og   = (const float*)d_in[9];
    const float* ob   = (const float*)d_in[10];
    const float* tg   = (const float*)d_in[11];
    const float* tb2  = (const float*)d_in[12];
    const float* pg   = (const float*)d_in[13];
    const float* pb   = (const float*)d_in[14];
    const float* sW   = (const float*)d_in[15];
    const float* sb   = (const float*)d_in[16];
    const float* tuW  = (const float*)d_in[17];
    const float* puW  = (const float*)d_in[18];
    const float* bs   = (const float*)d_in[19];
    float* out = (float*)d_out;

    const int GEMM_SMEM = 128 * 132 * 4;  // 67584 B (>= 3-stage pipeline footprint 56832)
    cudaFuncSetAttribute(k_gemm<1>, cudaFuncAttributeMaxDynamicSharedMemorySize, GEMM_SMEM);
    cudaFuncSetAttribute(k_gemm<2>, cudaFuncAttributeMaxDynamicSharedMemorySize, GEMM_SMEM);
    cudaFuncSetAttribute(k_gemm<3>, cudaFuncAttributeMaxDynamicSharedMemorySize, GEMM_SMEM);

    __nv_bfloat16 *w1p, *w2p, *w3p;
    cudaGetSymbolAddress((void**)&w1p, g_w1);
    cudaGetSymbolAddress((void**)&w2p, g_w2);
    cudaGetSymbolAddress((void**)&w3p, g_w3);
    __nv_bfloat16 *catp, *a2p, *a3p;
    cudaGetSymbolAddress((void**)&catp, g_cat);
    cudaGetSymbolAddress((void**)&a2p, g_a2);
    cudaGetSymbolAddress((void**)&a3p, g_a3);

    // weight conversions (tiny)
    k_cvt<<<(2048 * DD / 4 + 255) / 256, 256>>>(sW, w1p, 2048 * DD / 4);
    k_cvt<<<(DD * DD / 4 + 255) / 256, 256>>>(tuW, w2p, DD * DD / 4);
    k_cvt<<<(DD * DD / 4 + 255) / 256, 256>>>(puW, w3p, DD * DD / 4);

    k_scores<<<NROWS / 8, 256>>>(pt, aw, ab);
    k_top3<<<BB, 256>>>(pos);
    k_basis<<<BB * KA * MM, 128>>>(pt, cent, ta);
    k_mix<<<BB * KA, 128>>>(pos);
    k_translate<<<BB * KA * MM, 128>>>(tb);
    k_tcombine<<<BB * KA, 256>>>();
    k_rows<<<NROWS, 256>>>(ts, pt, pos, stab, og, ob, tg, tb2, pg, pb);

    dim3 gg(8, 256);
    k_gemm<1><<<gg, 256, GEMM_SMEM>>>(catp, 2 * DD, w1p, sb, sW + (size_t)2048 * DD,
                                      nullptr, nullptr, nullptr, 2048);
    k_pool<<<NROWS, 256>>>();
    k_gemm<2><<<gg, 256, GEMM_SMEM>>>(a2p, DD, w2p, nullptr, nullptr,
                                      nullptr, bs, out, 1024);
    k_gemm<3><<<gg, 256, GEMM_SMEM>>>(a3p, DD, w3p, nullptr, nullptr,
                                      pt, bs, out + (size_t)NROWS * DD, 1024);
}

// round 9
// speedup vs baseline: 2.1283x; 1.4253x over previous
#include <cuda_runtime.h>
#include <cuda_bf16.h>
#include <cstdint>

#define BB 8
#define SS 4096
#define DD 1024
#define MM 32
#define KA 3
#define RR 64
#define NROWS (BB*SS)

// ---------------- scratch (device globals; no allocations allowed) ----------------
__device__ float g_scores[NROWS];
__device__ int   g_aidx[BB*KA];
__device__ float g_apos[BB*KA];
__device__ float g_logits[BB*KA*MM];
__device__ float g_ua[BB*KA*MM*RR];
__device__ float g_w[BB*KA*MM];
__device__ float g_low[BB*KA*RR];
__device__ float g_Z[BB*KA];
__device__ float g_transp[BB*KA*MM*DD];
__device__ float g_trans[BB*KA*DD];
__device__ float g_tsaug[(size_t)NROWS*DD];
__device__ float g_gate[NROWS];
__device__ float g_shared[(size_t)NROWS*DD];
__device__ __align__(16) __nv_bfloat16 g_cat[(size_t)NROWS*2*DD];   // [tsn|ptn] bf16
__device__ __align__(16) __nv_bfloat16 g_a2[(size_t)NROWS*DD];
__device__ __align__(16) __nv_bfloat16 g_a3[(size_t)NROWS*DD];
__device__ __align__(16) __nv_bfloat16 g_w1[(size_t)2048*DD];       // shared_W[0:2048] bf16
__device__ __align__(16) __nv_bfloat16 g_w2[(size_t)DD*DD];         // ts_up_W bf16
__device__ __align__(16) __nv_bfloat16 g_w3[(size_t)DD*DD];         // pt_up_W bf16

// ---------------- cp.async helpers ----------------
__device__ __forceinline__ void cp16s(unsigned int dst_sh, const void* src) {
    asm volatile("cp.async.cg.shared.global [%0], [%1], 16;\n" :: "r"(dst_sh), "l"(src));
}
#define CP_COMMIT() asm volatile("cp.async.commit_group;\n" ::: "memory")
#define CP_WAIT1()  asm volatile("cp.async.wait_group 1;\n" ::: "memory")
#define CP_WAIT0()  asm volatile("cp.async.wait_group 0;\n" ::: "memory")

// ---------------- weight fp32 -> bf16 ----------------
__global__ void __launch_bounds__(256) k_cvt(const float* __restrict__ src,
                                             __nv_bfloat16* __restrict__ dst, int n4) {
    int i = blockIdx.x * blockDim.x + threadIdx.x;
    if (i >= n4) return;
    float4 v = ((const float4*)src)[i];
    __nv_bfloat162* o = (__nv_bfloat162*)dst + i * 2;
    o[0] = __floats2bfloat162_rn(v.x, v.y);
    o[1] = __floats2bfloat162_rn(v.z, v.w);
}

// ---------------- K0: anchor scores ----------------
__global__ void __launch_bounds__(256) k_scores(const float* __restrict__ pt,
                                                const float* __restrict__ aw,
                                                const float* __restrict__ ab) {
    int gw = (blockIdx.x * blockDim.x + threadIdx.x) >> 5;
    int lane = threadIdx.x & 31;
    if (gw >= NROWS) return;
    const float4* p = (const float4*)(pt + (size_t)gw * DD);
    const float4* w = (const float4*)aw;
    float s = 0.f;
#pragma unroll
    for (int i = 0; i < 8; i++) {
        float4 a = p[lane + 32 * i];
        float4 b = w[lane + 32 * i];
        s += a.x * b.x + a.y * b.y + a.z * b.z + a.w * b.w;
    }
#pragma unroll
    for (int o = 16; o; o >>= 1) s += __shfl_down_sync(0xffffffffu, s, o);
    if (!lane) g_scores[gw] = s + ab[0];
}

// ---------------- K1: top-3 per batch ----------------
__global__ void k_top3(const float* __restrict__ pos) {
    __shared__ float sv[256];
    __shared__ int   si[256];
    __shared__ int   chosen[KA];
    int b = blockIdx.x, tid = threadIdx.x;
    const float* sc = g_scores + b * SS;
    for (int k = 0; k < KA; k++) {
        float bv = -3.4e38f; int bi = SS;
        for (int s = tid; s < SS; s += 256) {
            bool used = false;
            for (int j = 0; j < k; j++) used |= (chosen[j] == s);
            if (used) continue;
            float v = sc[s];
            if (v > bv || (v == bv && s < bi)) { bv = v; bi = s; }
        }
        sv[tid] = bv; si[tid] = bi;
        __syncthreads();
        for (int o = 128; o; o >>= 1) {
            if (tid < o) {
                if (sv[tid + o] > sv[tid] || (sv[tid + o] == sv[tid] && si[tid + o] < si[tid])) {
                    sv[tid] = sv[tid + o]; si[tid] = si[tid + o];
                }
            }
            __syncthreads();
        }
        if (tid == 0) {
            chosen[k] = si[0];
            g_aidx[b * KA + k] = si[0];
            g_apos[b * KA + k] = pos[si[0]];
        }
        __syncthreads();
    }
}

// ---------------- K2: per (b,k,m): cosine logit + u_a ----------------
__global__ void __launch_bounds__(128) k_basis(const float* __restrict__ pt,
                                               const float* __restrict__ cent,
                                               const float* __restrict__ ta) {
    __shared__ float av[DD];
    __shared__ float r1[128], r2[128], r3[128];
    int id = blockIdx.x;
    int m = id % MM, bk = id / MM;
    int b = bk / KA;
    int tid = threadIdx.x;
    const float* prow = pt + ((size_t)b * SS + g_aidx[bk]) * DD;
    const float* crow = cent + (size_t)m * DD;
    float pa = 0.f, pc = 0.f, pd = 0.f;
    for (int d = tid; d < DD; d += 128) {
        float a = prow[d], c = crow[d];
        av[d] = a; pa += a * a; pc += c * c; pd += a * c;
    }
    r1[tid] = pa; r2[tid] = pc; r3[tid] = pd;
    __syncthreads();
    for (int o = 64; o; o >>= 1) {
        if (tid < o) { r1[tid] += r1[tid + o]; r2[tid] += r2[tid + o]; r3[tid] += r3[tid + o]; }
        __syncthreads();
    }
    if (tid == 0) {
        float na = sqrtf(r1[0]), nc = sqrtf(r2[0]);
        g_logits[id] = r3[0] / (fmaxf(na, 1e-6f) * fmaxf(nc, 1e-6f));
    }
    __syncthreads();
    int r = tid & 63, h = tid >> 6;
    const float* tap = ta + (size_t)m * DD * RR + r;
    float u = 0.f;
    int d0 = h * 512;
#pragma unroll 8
    for (int d = d0; d < d0 + 512; d++) u += av[d] * tap[(size_t)d * RR];
    r1[tid] = u;
    __syncthreads();
    if (h == 0) g_ua[(size_t)id * RR + r] = r1[r] + r1[r + 64];
}

// ---------------- K3: per (b,k): softmax, low, spread normalizer ----------------
__global__ void __launch_bounds__(128) k_mix(const float* __restrict__ pos) {
    __shared__ float w[MM];
    __shared__ float red[128];
    int bk = blockIdx.x, tid = threadIdx.x;
    if (tid == 0) {
        float mx = -3.4e38f;
        for (int m = 0; m < MM; m++) mx = fmaxf(mx, g_logits[bk * MM + m]);
        float ssum = 0.f;
        for (int m = 0; m < MM; m++) { float e = expf(g_logits[bk * MM + m] - mx); w[m] = e; ssum += e; }
        float inv = 1.0f / ssum;
        for (int m = 0; m < MM; m++) w[m] *= inv;
    }
    __syncthreads();
    if (tid < MM) g_w[bk * MM + tid] = w[tid];
    if (tid < RR) {
        float lo = 0.f;
        for (int m = 0; m < MM; m++) lo += w[m] * g_ua[(size_t)(bk * MM + m) * RR + tid];
        g_low[bk * RR + tid] = lo;
    }
    float p = g_apos[bk];
    float z = 0.f;
    for (int s = tid; s < SS; s += 128) {
        float d = fabsf(pos[s] - p);
        if (d <= 8.0f) z += expf(-d * 0.125f);
    }
    red[tid] = z;
    __syncthreads();
    for (int o = 64; o; o >>= 1) { if (tid < o) red[tid] += red[tid + o]; __syncthreads(); }
    if (tid == 0) g_Z[bk] = red[0];
}

// ---------------- K4: per (b,k,m): partial translated ----------------
__global__ void __launch_bounds__(128) k_translate(const float* __restrict__ tb) {
    __shared__ float low[RR];
    __shared__ float wv;
    int id = blockIdx.x;
    int m = id % MM, bk = id / MM;
    int tid = threadIdx.x;
    if (tid < RR) low[tid] = g_low[bk * RR + tid];
    if (tid == 0) wv = g_w[bk * MM + m];
    __syncthreads();
    float wloc = wv;
    const float4* base = (const float4*)(tb + (size_t)m * DD * RR);
#pragma unroll
    for (int j = 0; j < 8; j++) {
        int d = tid + 128 * j;
        const float4* rp = base + (size_t)d * (RR / 4);
        float acc = 0.f;
#pragma unroll
        for (int i = 0; i < 16; i++) {
            float4 v = rp[i];
            acc += low[4 * i] * v.x + low[4 * i + 1] * v.y + low[4 * i + 2] * v.z + low[4 * i + 3] * v.w;
        }
        g_transp[(size_t)id * DD + d] = wloc * acc;
    }
}

__global__ void __launch_bounds__(256) k_tcombine() {
    int bk = blockIdx.x, tid = threadIdx.x;
    for (int d = tid; d < DD; d += 256) {
        float s = 0.f;
        for (int m = 0; m < MM; m++) s += g_transp[(size_t)(bk * MM + m) * DD + d];
        g_trans[bk * DD + d] = s;
    }
}

// ---------------- block reduce helper ----------------
__device__ __forceinline__ float2 bred2(float2 v, float* red) {
    int tid = threadIdx.x;
#pragma unroll
    for (int o = 16; o; o >>= 1) {
        v.x += __shfl_down_sync(0xffffffffu, v.x, o);
        v.y += __shfl_down_sync(0xffffffffu, v.y, o);
    }
    if ((tid & 31) == 0) { red[tid >> 5] = v.x; red[8 + (tid >> 5)] = v.y; }
    __syncthreads();
    if (tid == 0) {
        float a = 0.f, b = 0.f;
        for (int i = 0; i < 8; i++) { a += red[i]; b += red[8 + i]; }
        red[0] = a; red[8] = b;
    }
    __syncthreads();
    float2 r = make_float2(red[0], red[8]);
    __syncthreads();
    return r;
}

// ---------------- K5: fused row kernel (anchor update + 3 LNs + gate) ----------------
__global__ void __launch_bounds__(256) k_rows(
    const float* __restrict__ ts, const float* __restrict__ pt,
    const float* __restrict__ pos, const float* __restrict__ stab,
    const float* __restrict__ og, const float* __restrict__ ob,
    const float* __restrict__ tg, const float* __restrict__ tb2,
    const float* __restrict__ pg, const float* __restrict__ pb) {
    __shared__ float red[16];
    int row = blockIdx.x;
    int b = row / SS, s = row % SS;
    int tid = threadIdx.x;
    size_t base = (size_t)row * DD;
    float4 tsv = ((const float4*)(ts + base))[tid];
    float4 ptv = ((const float4*)(pt + base))[tid];
    float ps = pos[s];
    float4 upd = make_float4(0.f, 0.f, 0.f, 0.f);
#pragma unroll
    for (int k = 0; k < KA; k++) {
        int bk = b * KA + k;
        float dist = fabsf(ps - g_apos[bk]);
        if (dist <= 8.0f) {
            float c = expf(-dist * 0.125f) / g_Z[bk];
            float4 t = ((const float4*)(g_trans + (size_t)bk * DD))[tid];
            upd.x += c * t.x; upd.y += c * t.y; upd.z += c * t.z; upd.w += c * t.w;
        }
    }
    float4 x = make_float4(tsv.x + upd.x, tsv.y + upd.y, tsv.z + upd.z, tsv.w + upd.w);
    const float invD = 1.0f / DD;
    float2 s1 = bred2(make_float2(x.x + x.y + x.z + x.w,
                                  x.x * x.x + x.y * x.y + x.z * x.z + x.w * x.w), red);
    float mu = s1.x * invD;
    float var = s1.y * invD - mu * mu;
    float rs = rsqrtf(var + 1e-5f);
    float4 gv = ((const float4*)og)[tid], bv = ((const float4*)ob)[tid];
    float4 aug;
    aug.x = (x.x - mu) * rs * gv.x + bv.x;
    aug.y = (x.y - mu) * rs * gv.y + bv.y;
    aug.z = (x.z - mu) * rs * gv.z + bv.z;
    aug.w = (x.w - mu) * rs * gv.w + bv.w;
    ((float4*)(g_tsaug + base))[tid] = aug;
    float2 s2 = bred2(make_float2(aug.x + aug.y + aug.z + aug.w,
                                  aug.x * aug.x + aug.y * aug.y + aug.z * aug.z + aug.w * aug.w), red);
    float mu2 = s2.x * invD;
    float rs2 = rsqrtf(s2.y * invD - mu2 * mu2 + 1e-5f);
    float4 gv2 = ((const float4*)tg)[tid], bv2 = ((const float4*)tb2)[tid];
    float4 tn;
    tn.x = (aug.x - mu2) * rs2 * gv2.x + bv2.x;
    tn.y = (aug.y - mu2) * rs2 * gv2.y + bv2.y;
    tn.z = (aug.z - mu2) * rs2 * gv2.z + bv2.z;
    tn.w = (aug.w - mu2) * rs2 * gv2.w + bv2.w;
    float2 s3 = bred2(make_float2(ptv.x + ptv.y + ptv.z + ptv.w,
                                  ptv.x * ptv.x + ptv.y * ptv.y + ptv.z * ptv.z + ptv.w * ptv.w), red);
    float mu3 = s3.x * invD;
    float rs3 = rsqrtf(s3.y * invD - mu3 * mu3 + 1e-5f);
    float4 gv3 = ((const float4*)pg)[tid], bv3 = ((const float4*)pb)[tid];
    float4 pn;
    pn.x = (ptv.x - mu3) * rs3 * gv3.x + bv3.x;
    pn.y = (ptv.y - mu3) * rs3 * gv3.y + bv3.y;
    pn.z = (ptv.z - mu3) * rs3 * gv3.z + bv3.z;
    pn.w = (ptv.w - mu3) * rs3 * gv3.w + bv3.w;
    {
        __nv_bfloat162* ct = (__nv_bfloat162*)(g_cat + (size_t)row * 2 * DD) + tid * 2;
        ct[0] = __floats2bfloat162_rn(tn.x, tn.y);
        ct[1] = __floats2bfloat162_rn(tn.z, tn.w);
        __nv_bfloat162* cp2 = (__nv_bfloat162*)(g_cat + (size_t)row * 2 * DD + DD) + tid * 2;
        cp2[0] = __floats2bfloat162_rn(pn.x, pn.y);
        cp2[1] = __floats2bfloat162_rn(pn.z, pn.w);
    }
    float2 s4 = bred2(make_float2(tn.x * pn.x + tn.y * pn.y + tn.z * pn.z + tn.w * pn.w,
                                  tn.x * tn.x + tn.y * tn.y + tn.z * tn.z + tn.w * tn.w), red);
    float2 s5 = bred2(make_float2(pn.x * pn.x + pn.y * pn.y + pn.z * pn.z + pn.w * pn.w, 0.f), red);
    if (tid == 0) {
        float cosv = s4.x / (fmaxf(sqrtf(s4.y), 1e-6f) * fmaxf(sqrtf(s5.x), 1e-6f));
        float ag = 0.5f * (1.0f + cosv);
        float z = (ag - 0.72f) / 0.2f;
        float focus = 0.2f + 0.8f * expf(-0.5f * z * z);
        g_gate[row] = ag * focus * stab[row];
    }
}

// ---------------- K7: causal pool + form bf16 GEMM inputs ----------------
__global__ void __launch_bounds__(256) k_pool() {
    int row = blockIdx.x;
    int b = row / SS, s = row % SS;
    int tid = threadIdx.x;
    size_t base = (size_t)row * DD;
    int s1 = s - 1; if (s1 < 0) s1 = 0;
    int s2 = s - 2; if (s2 < 0) s2 = 0;
    size_t b1 = ((size_t)b * SS + s1) * DD;
    size_t b2 = ((size_t)b * SS + s2) * DD;
    float4 x0 = ((const float4*)(g_shared + base))[tid];
    float4 x1 = ((const float4*)(g_shared + b1))[tid];
    float4 x2 = ((const float4*)(g_shared + b2))[tid];
    float4 pl;
    pl.x = (x0.x + x1.x + x2.x) / 3.0f;
    pl.y = (x0.y + x1.y + x2.y) / 3.0f;
    pl.z = (x0.z + x1.z + x2.z) / 3.0f;
    pl.w = (x0.w + x1.w + x2.w) / 3.0f;
    const __nv_bfloat162* ct = (const __nv_bfloat162*)(g_cat + (size_t)row * 2 * DD) + tid * 2;
    const __nv_bfloat162* cp2 = (const __nv_bfloat162*)(g_cat + (size_t)row * 2 * DD + DD) + tid * 2;
    float2 t01 = __bfloat1622float2(ct[0]);
    float2 t23 = __bfloat1622float2(ct[1]);
    float2 p01 = __bfloat1622float2(cp2[0]);
    float2 p23 = __bfloat1622float2(cp2[1]);
    __nv_bfloat162* o2 = (__nv_bfloat162*)(g_a2 + base) + tid * 2;
    o2[0] = __floats2bfloat162_rn(pl.x - t01.x, pl.y - t01.y);
    o2[1] = __floats2bfloat162_rn(pl.z - t23.x, pl.w - t23.y);
    __nv_bfloat162* o3 = (__nv_bfloat162*)(g_a3 + base) + tid * 2;
    o3[0] = __floats2bfloat162_rn(pl.x - p01.x, pl.y - p01.y);
    o3[1] = __floats2bfloat162_rn(pl.z - p23.x, pl.w - p23.y);
}

// ---------------- raw mma.sync bf16 GEMM ----------------
// block 128x128, BK=64, 3-stage cp.async, 256 threads (8 warps, warp tile 32x64)
// A smem: 128 rows x 128B (swizzle kc^=m&7);  B smem: 64 rows x 256B (swizzle nc^=k&15)
// Epilogue from registers (m16n8k16 accumulator mapping), no smem staging.
#define STG_BYTES 32768          // 16KB A + 16KB B per stage
#define GEMM_SMEM (3*STG_BYTES)  // 98304

template<int MODE>
__global__ void __launch_bounds__(256) k_gemm(const __nv_bfloat16* __restrict__ A, int lda,
                                              const __nv_bfloat16* __restrict__ Bw,
                                              const float* __restrict__ bias,
                                              const float* __restrict__ wlast,
                                              const float* __restrict__ basept,
                                              const float* __restrict__ bscale,
                                              float* __restrict__ outp, int Ktot) {
    extern __shared__ char smem_raw[];
    const unsigned int sbase = (unsigned int)__cvta_generic_to_shared(smem_raw);
    const int tid = threadIdx.x, lane = tid & 31, wid = tid >> 5;
    const int wm = wid & 3, wn = wid >> 2;
    const int row0 = blockIdx.y * 128, col0 = blockIdx.x * 128;

    float acc[2][8][4];
#pragma unroll
    for (int i = 0; i < 2; i++)
#pragma unroll
        for (int j = 0; j < 8; j++)
#pragma unroll
            for (int q = 0; q < 4; q++) acc[i][j][q] = 0.0f;

    const int nIter = Ktot >> 6;

    auto load_stage = [&](int s, int kt) {
        unsigned int ab = sbase + s * STG_BYTES;
        unsigned int bb = ab + 16384;
#pragma unroll
        for (int p = 0; p < 4; p++) {
            int id = tid + 256 * p;
            int m = id >> 3, kc = id & 7;
            cp16s(ab + m * 128 + ((kc ^ (m & 7)) << 4),
                  A + (size_t)(row0 + m) * lda + kt * 64 + kc * 8);
            int k = id >> 4, nc = id & 15;
            cp16s(bb + k * 256 + ((nc ^ (k & 15)) << 4),
                  Bw + (size_t)(kt * 64 + k) * DD + col0 + nc * 8);
        }
        CP_COMMIT();
    };

    load_stage(0, 0);
    load_stage(1, 1);

    int st = 0;
    for (int it = 0; it < nIter; it++) {
        CP_WAIT1();
        __syncthreads();
        unsigned int ab = sbase + st * STG_BYTES;
        unsigned int bb = ab + 16384;
#pragma unroll
        for (int kk = 0; kk < 4; kk++) {
            unsigned int af[2][4], bf[8][2];
#pragma unroll
            for (int i = 0; i < 2; i++) {
                int r = wm * 32 + i * 16 + (lane & 15);
                int kc = kk * 2 + (lane >> 4);
                unsigned int addr = ab + r * 128 + ((kc ^ (r & 7)) << 4);
                asm volatile("ldmatrix.sync.aligned.m8n8.x4.shared.b16 {%0,%1,%2,%3}, [%4];"
                    : "=r"(af[i][0]), "=r"(af[i][1]), "=r"(af[i][2]), "=r"(af[i][3])
                    : "r"(addr));
            }
#pragma unroll
            for (int j = 0; j < 4; j++) {
                int r = kk * 16 + (lane & 7) + ((lane >> 3) & 1) * 8;
                int nc = wn * 8 + j * 2 + (lane >> 4);
                unsigned int addr = bb + r * 256 + ((nc ^ (r & 15)) << 4);
                asm volatile("ldmatrix.sync.aligned.m8n8.x4.trans.shared.b16 {%0,%1,%2,%3}, [%4];"
                    : "=r"(bf[2*j][0]), "=r"(bf[2*j][1]), "=r"(bf[2*j+1][0]), "=r"(bf[2*j+1][1])
                    : "r"(addr));
            }
#pragma unroll
            for (int i = 0; i < 2; i++)
#pragma unroll
                for (int j = 0; j < 8; j++)
                    asm volatile("mma.sync.aligned.m16n8k16.row.col.f32.bf16.bf16.f32 "
                        "{%0,%1,%2,%3}, {%4,%5,%6,%7}, {%8,%9}, {%0,%1,%2,%3};"
                        : "+f"(acc[i][j][0]), "+f"(acc[i][j][1]), "+f"(acc[i][j][2]), "+f"(acc[i][j][3])
                        : "r"(af[i][0]), "r"(af[i][1]), "r"(af[i][2]), "r"(af[i][3]),
                          "r"(bf[j][0]), "r"(bf[j][1]));
        }
        int nf = it + 2;
        if (nf < nIter) load_stage(nf - (nf / 3) * 3, nf);
        else CP_COMMIT();
        st++; if (st == 3) st = 0;
    }

    // epilogue straight from accumulator registers
    float blend = 0.0f;
    if (MODE != 1) blend = 0.35f / (1.0f + expf(-bscale[0]));
#pragma unroll
    for (int i = 0; i < 2; i++) {
        int rb = row0 + wm * 32 + i * 16 + (lane >> 2);
#pragma unroll
        for (int h = 0; h < 2; h++) {
            int r = rb + h * 8;
            float g = g_gate[r];
            float lb = blend * g;
#pragma unroll
            for (int j = 0; j < 8; j++) {
                int c = col0 + wn * 64 + j * 8 + (lane & 3) * 2;
                float v0 = acc[i][j][h * 2], v1 = acc[i][j][h * 2 + 1];
                if (MODE == 1) {
                    float2 bi = *(const float2*)(bias + c);
                    float2 wl = *(const float2*)(wlast + c);
                    float2 o = make_float2(v0 + bi.x + g * wl.x, v1 + bi.y + g * wl.y);
                    *(float2*)(g_shared + (size_t)r * DD + c) = o;
                } else {
                    const float* bp = (MODE == 2 ? g_tsaug : basept) + (size_t)r * DD + c;
                    float2 b2 = *(const float2*)bp;
                    float2 o = make_float2(b2.x + lb * v0, b2.y + lb * v1);
                    *(float2*)(outp + (size_t)r * DD + c) = o;
                }
            }
        }
    }
}

// ---------------- launch ----------------
extern "C" void kernel_launch(void* const* d_in, const int* in_sizes, int n_in,
                              void* d_out, int out_size) {
    const float* pt   = (const float*)d_in[0];
    const float* ts   = (const float*)d_in[1];
    const float* pos  = (const float*)d_in[2];
    const float* cent = (const float*)d_in[3];
    const float* stab = (const float*)d_in[4];
    const float* aw   = (const float*)d_in[5];
    const float* ab   = (const float*)d_in[6];
    const float* ta   = (const float*)d_in[7];
    const float* tb   = (const float*)d_in[8];
    const float* og   = (const float*)d_in[9];
    const float* ob   = (const float*)d_in[10];
    const float* tg   = (const float*)d_in[11];
    const float* tb2  = (const float*)d_in[12];
    const float* pg   = (const float*)d_in[13];
    const float* pb   = (const float*)d_in[14];
    const float* sW   = (const float*)d_in[15];
    const float* sb   = (const float*)d_in[16];
    const float* tuW  = (const float*)d_in[17];
    const float* puW  = (const float*)d_in[18];
    const float* bs   = (const float*)d_in[19];
    float* out = (float*)d_out;

    cudaFuncSetAttribute(k_gemm<1>, cudaFuncAttributeMaxDynamicSharedMemorySize, GEMM_SMEM);
    cudaFuncSetAttribute(k_gemm<2>, cudaFuncAttributeMaxDynamicSharedMemorySize, GEMM_SMEM);
    cudaFuncSetAttribute(k_gemm<3>, cudaFuncAttributeMaxDynamicSharedMemorySize, GEMM_SMEM);

    __nv_bfloat16 *w1p, *w2p, *w3p;
    cudaGetSymbolAddress((void**)&w1p, g_w1);
    cudaGetSymbolAddress((void**)&w2p, g_w2);
    cudaGetSymbolAddress((void**)&w3p, g_w3);
    __nv_bfloat16 *catp, *a2p, *a3p;
    cudaGetSymbolAddress((void**)&catp, g_cat);
    cudaGetSymbolAddress((void**)&a2p, g_a2);
    cudaGetSymbolAddress((void**)&a3p, g_a3);

    // weight conversions (tiny)
    k_cvt<<<(2048 * DD / 4 + 255) / 256, 256>>>(sW, w1p, 2048 * DD / 4);
    k_cvt<<<(DD * DD / 4 + 255) / 256, 256>>>(tuW, w2p, DD * DD / 4);
    k_cvt<<<(DD * DD / 4 + 255) / 256, 256>>>(puW, w3p, DD * DD / 4);

    k_scores<<<NROWS / 8, 256>>>(pt, aw, ab);
    k_top3<<<BB, 256>>>(pos);
    k_basis<<<BB * KA * MM, 128>>>(pt, cent, ta);
    k_mix<<<BB * KA, 128>>>(pos);
    k_translate<<<BB * KA * MM, 128>>>(tb);
    k_tcombine<<<BB * KA, 256>>>();
    k_rows<<<NROWS, 256>>>(ts, pt, pos, stab, og, ob, tg, tb2, pg, pb);

    dim3 gg(8, 256);
    k_gemm<1><<<gg, 256, GEMM_SMEM>>>(catp, 2 * DD, w1p, sb, sW + (size_t)2048 * DD,
                                      nullptr, nullptr, nullptr, 2048);
    k_pool<<<NROWS, 256>>>();
    k_gemm<2><<<gg, 256, GEMM_SMEM>>>(a2p, DD, w2p, nullptr, nullptr,
                                      nullptr, bs, out, 1024);
    k_gemm<3><<<gg, 256, GEMM_SMEM>>>(a3p, DD, w3p, nullptr, nullptr,
                                      pt, bs, out + (size_t)NROWS * DD, 1024);
}